// round 15
// baseline (speedup 1.0000x reference)
#include <cuda_runtime.h>
#include <cstdint>

#define BB 8
#define NN 2048
#define KK 20
#define CATC 512

// ---------------- static scratch (no allocations allowed) ----------------
__device__ unsigned g_Dk[(size_t)BB * NN * NN];  // 134 MB pairwise dist as order-preserving keys
__device__ int   g_idx[BB * NN * KK];            // knn indices
__device__ float g_xx[BB * NN];                  // per-point squared norms
__device__ float g_cat[(size_t)BB * NN * CATC];  // concat feature buffer (B,N,512)
__device__ float g_t[(size_t)BB * NN * 256];     // center-term GEMM output (B,N,O)
__device__ float g_t2[(size_t)BB * NN * 256];    // neighbor-term dense GEMM output
__device__ float g_h5[(size_t)BB * NN * 512];    // final conv pre-norm
__device__ float g_partS[(size_t)8 * 2 * 512 * 128]; // per-block partial sums
__device__ float g_partQ[(size_t)8 * 2 * 512 * 128]; // per-block partial sumsq
__device__ float g_sum[BB * 512];
__device__ float g_sumsq[BB * 512];

// order-preserving float -> uint key (strictly monotone, bijective)
__device__ __forceinline__ unsigned f2k(float f) {
    unsigned u = __float_as_uint(f);
    return (u & 0x80000000u) ? ~u : (u | 0x80000000u);
}

// ---------------- xx: per-point squared norm ----------------
__global__ void xx_kernel(const float* __restrict__ xin, int use_in, int xoff, int C) {
    int i = blockIdx.x * blockDim.x + threadIdx.x;
    if (i >= BB * NN) return;
    const float* p = use_in ? (xin + (size_t)i * 3) : (g_cat + (size_t)i * CATC + xoff);
    float s = 0.f;
    for (int c = 0; c < C; ++c) s += p[c] * p[c];
    g_xx[i] = s;
}

// ---------------- distance GEMM (block-triangular + mirror) ----------------
// Hoisted addressing: per-thread global pointers advance by +16 floats/chunk;
// smem store offsets are 32-bit immediates into unified S[2] buffer.
__global__ void dist_gemm(const float* __restrict__ xin, int use_in, int xoff, int C) {
    __shared__ __align__(16) float S[2][16][132];
    int b = blockIdx.z;
    int t = blockIdx.x;
    int bi = 0;
    while (t >= 16 - bi) { t -= 16 - bi; ++bi; }
    int bj = bi + t;
    int n0 = bi * 128, m0 = bj * 128;
    int tid = threadIdx.x, tx = tid & 15, ty = tid >> 4;
    float acc[8][8] = {};
    int nch = (C + 15) >> 4;
    // hoisted per-thread addressing (loop-invariant across chunks)
    float* sp[4];
    const float* gp[4];
#pragma unroll
    for (int ii = 0; ii < 4; ++ii) {
        int q4 = tid + ii * 256;
        int which = q4 >> 9, r = (q4 & 511) >> 2, cc4 = q4 & 3;
        sp[ii] = &S[which][cc4 * 4][r];
        int rowg = b * NN + (which ? m0 : n0) + r;
        gp[ii] = use_in ? (xin + (size_t)rowg * 3)
                        : (g_cat + (size_t)rowg * CATC + xoff + cc4 * 4);
    }
    float4 rg[4];
    // prefetch chunk 0
    if (use_in) {
#pragma unroll
        for (int ii = 0; ii < 4; ++ii) {
            int q4 = tid + ii * 256;
            int cc4 = q4 & 3;
            int c = cc4 * 4;
            float v[4];
#pragma unroll
            for (int e = 0; e < 4; ++e)
                v[e] = (c + e < C) ? gp[ii][c + e] : 0.f;
            rg[ii] = make_float4(v[0], v[1], v[2], v[3]);
        }
    } else {
#pragma unroll
        for (int ii = 0; ii < 4; ++ii) rg[ii] = *(const float4*)gp[ii];
    }
    for (int ch = 0; ch < nch; ++ch) {
#pragma unroll
        for (int ii = 0; ii < 4; ++ii) {
            float4 v = rg[ii];
            sp[ii][0 * 132] = v.x;
            sp[ii][1 * 132] = v.y;
            sp[ii][2 * 132] = v.z;
            sp[ii][3 * 132] = v.w;
        }
        __syncthreads();
        if (ch + 1 < nch) {
            // chunks >0 only occur for the g_cat path (C multiple of 16)
            int off = (ch + 1) * 16;
#pragma unroll
            for (int ii = 0; ii < 4; ++ii)
                rg[ii] = *(const float4*)(gp[ii] + off);
        }
#pragma unroll
        for (int cc = 0; cc < 16; ++cc) {
            float4 a0 = *(const float4*)&S[0][cc][ty * 8];
            float4 a1 = *(const float4*)&S[0][cc][ty * 8 + 4];
            float4 b0 = *(const float4*)&S[1][cc][tx * 8];
            float4 b1 = *(const float4*)&S[1][cc][tx * 8 + 4];
            float aa[8] = {a0.x, a0.y, a0.z, a0.w, a1.x, a1.y, a1.z, a1.w};
            float bb[8] = {b0.x, b0.y, b0.z, b0.w, b1.x, b1.y, b1.z, b1.w};
#pragma unroll
            for (int i = 0; i < 8; ++i)
#pragma unroll
                for (int j = 0; j < 8; ++j)
                    acc[i][j] = fmaf(aa[i], bb[j], acc[i][j]);
        }
        __syncthreads();
    }
    float xn[8], xm[8];
#pragma unroll
    for (int i = 0; i < 8; ++i) xn[i] = g_xx[b * NN + n0 + ty * 8 + i];
#pragma unroll
    for (int j = 0; j < 8; ++j) xm[j] = g_xx[b * NN + m0 + tx * 8 + j];
#pragma unroll
    for (int i = 0; i < 8; ++i) {
        unsigned k[8];
#pragma unroll
        for (int j = 0; j < 8; ++j) k[j] = f2k(2.f * acc[i][j] - xn[i] - xm[j]);
        size_t base = ((size_t)(b * NN + n0 + ty * 8 + i)) * NN + m0 + tx * 8;
        *(uint4*)&g_Dk[base] = make_uint4(k[0], k[1], k[2], k[3]);
        *(uint4*)&g_Dk[base + 4] = make_uint4(k[4], k[5], k[6], k[7]);
    }
    if (bi != bj) {
        unsigned (*Tu)[132] = (unsigned (*)[132])&S[0][0][0];
#pragma unroll
        for (int g = 0; g < 8; ++g) {
            if ((tx >> 1) == g) {
#pragma unroll
                for (int j = 0; j < 8; ++j)
#pragma unroll
                    for (int i = 0; i < 8; ++i)
                        Tu[(tx & 1) * 8 + j][ty * 8 + i] = f2k(2.f * acc[i][j] - xm[j] - xn[i]);
            }
            __syncthreads();
            for (int q = tid; q < 512; q += 256) {
                int lr = q >> 5;
                int fc = (q & 31) * 4;
                size_t base = ((size_t)(b * NN + m0 + g * 16 + lr)) * NN + n0 + fc;
                *(uint4*)&g_Dk[base] = *(const uint4*)&Tu[lr][fc];
            }
            __syncthreads();
        }
    }
}

// ---------------- top-K=20: radix select, 256 threads, histogram fused into load ------
// Output order identical to 20x iterative argmax with lowest-index tie-break.
__global__ void topk_kernel() {
    __shared__ unsigned keys[NN];
    __shared__ int candA[NN];
    __shared__ int candB[NN];
    __shared__ unsigned hist[256];
    __shared__ unsigned suf[256];
    __shared__ unsigned wtot[8];
    __shared__ int      rmin[256];
    __shared__ unsigned selK[24];
    __shared__ int      selI[24];
    __shared__ int s_rem, s_sel, s_m, s_nc, s_nc2;

    int n = blockIdx.x, b = blockIdx.y;
    int tid = threadIdx.x;
    int lane = tid & 31, w = tid >> 5;
    size_t rowbase = (size_t)(b * NN + n);
    const uint4* row4 = (const uint4*)(g_Dk + rowbase * NN);

    if (tid == 0) { s_rem = KK; s_m = 0; s_nc = 0; }
    hist[tid] = 0u;
    __syncthreads();

    // load row + histogram top byte in one pass
    for (int i = tid; i < NN / 4; i += 256) {
        uint4 v = row4[i];
        keys[i * 4 + 0] = v.x;
        keys[i * 4 + 1] = v.y;
        keys[i * 4 + 2] = v.z;
        keys[i * 4 + 3] = v.w;
        atomicAdd(&hist[v.x >> 24], 1u);
        atomicAdd(&hist[v.y >> 24], 1u);
        atomicAdd(&hist[v.z >> 24], 1u);
        atomicAdd(&hist[v.w >> 24], 1u);
    }
    __syncthreads();

    int* cur = candA;
    int* nxt = candB;

#pragma unroll
    for (int p = 0; p < 4; ++p) {
        // suffix scan of hist -> suf (warp shuffles)
        {
            unsigned v = hist[tid];
#pragma unroll
            for (int d = 1; d < 32; d <<= 1) {
                unsigned o = __shfl_down_sync(0xffffffffu, v, d);
                if (lane + d < 32) v += o;
            }
            if (lane == 0) wtot[w] = v;
            __syncthreads();
            if (w == 0 && lane < 8) {
                unsigned t2 = wtot[lane];
#pragma unroll
                for (int d = 1; d < 8; d <<= 1) {
                    unsigned o = __shfl_down_sync(0xffu, t2, d);
                    if (lane + d < 8) t2 += o;
                }
                wtot[lane] = t2;
            }
            __syncthreads();
            unsigned add = (w < 7) ? wtot[w + 1] : 0u;
            suf[tid] = v + add;
            __syncthreads();
        }
        int rem = s_rem;
        if (suf[tid] >= (unsigned)rem && (tid == 255 || suf[tid + 1] < (unsigned)rem))
            s_sel = tid;
        __syncthreads();
        if (tid == 0) {
            int sel = s_sel;
            s_rem = rem - (int)((sel == 255) ? 0u : suf[sel + 1]);
            s_nc2 = 0;
        }
        __syncthreads();
        unsigned sel = (unsigned)s_sel;
        int shift = 24 - 8 * p;

        if (p == 0) {
            for (int i = tid; i < NN; i += 256) {
                unsigned byte = keys[i] >> 24;
                if (byte > sel) {
                    int pos = atomicAdd(&s_m, 1);
                    selK[pos] = keys[i]; selI[pos] = i;
                } else if (byte == sel) {
                    int pos = atomicAdd(&s_nc2, 1);
                    nxt[pos] = i;
                }
            }
        } else {
            int L = s_nc;
            for (int t2 = tid; t2 < L; t2 += 256) {
                int i = cur[t2];
                unsigned byte = (keys[i] >> shift) & 0xFFu;
                if (byte > sel) {
                    int pos = atomicAdd(&s_m, 1);
                    selK[pos] = keys[i]; selI[pos] = i;
                } else if (byte == sel) {
                    int pos = atomicAdd(&s_nc2, 1);
                    nxt[pos] = i;
                }
            }
        }
        __syncthreads();
        if (tid == 0) s_nc = s_nc2;
        hist[tid] = 0u;
        __syncthreads();
        if (p < 3) {
            int L = s_nc;
            int nshift = 24 - 8 * (p + 1);
            for (int t2 = tid; t2 < L; t2 += 256)
                atomicAdd(&hist[(keys[nxt[t2]] >> nshift) & 0xFFu], 1u);
            __syncthreads();
        }
        { int* tmp = cur; cur = nxt; nxt = tmp; }
    }

    int m = s_m;
    int r = s_rem;
    int L = s_nc;
    int* outp = g_idx + rowbase * KK;
    if (tid == 0) {
        for (int a = 1; a < m; ++a) {
            unsigned kk = selK[a]; int ii = selI[a];
            int bp = a - 1;
            while (bp >= 0 && (selK[bp] < kk || (selK[bp] == kk && selI[bp] > ii))) {
                selK[bp + 1] = selK[bp]; selI[bp + 1] = selI[bp]; --bp;
            }
            selK[bp + 1] = kk; selI[bp + 1] = ii;
        }
        for (int a = 0; a < m; ++a) outp[a] = selI[a];
    }
    __syncthreads();
    for (int round = 0; round < r; ++round) {
        int lm = 0x7FFFFFFF;
        for (int i = tid; i < L; i += 256) lm = min(lm, cur[i]);
        rmin[tid] = lm;
        __syncthreads();
#pragma unroll
        for (int s = 128; s > 0; s >>= 1) {
            if (tid < s) rmin[tid] = min(rmin[tid], rmin[tid + s]);
            __syncthreads();
        }
        int mv = rmin[0];
        if (tid == 0) outp[m + round] = mv;
        for (int i = tid; i < L; i += 256)
            if (cur[i] == mv) cur[i] = 0x7FFFFFFF;
        __syncthreads();
    }
}

// ---------------- merged small GEMM (layers 1-3): g_t and g_t2 from one A tile --------
__global__ void small_gemm2(const float* __restrict__ xin, int use_in, int xoff, int C,
                            const float* __restrict__ w, int O) {
    __shared__ __align__(16) float As[16][68];
    __shared__ __align__(16) float B0[16][68];
    __shared__ __align__(16) float B1[16][68];
    int r0 = blockIdx.y * 64, o0 = blockIdx.x * 64;
    int tid = threadIdx.x, tx = tid & 15, ty = tid >> 4;
    float acc0[4][4] = {};
    float acc1[4][4] = {};
    int twoC = 2 * C;
    int nch = (C + 15) >> 4;
    for (int ch = 0; ch < nch; ++ch) {
        int c0 = ch * 16;
        for (int t = tid; t < 3072; t += 256) {
            int which = t >> 10;
            int r = (t & 1023) >> 4;
            int cc = t & 15;
            int c = c0 + cc;
            float v = 0.f;
            if (which == 0) {
                if (c < C)
                    v = use_in ? xin[(size_t)(r0 + r) * 3 + c]
                               : g_cat[(size_t)(r0 + r) * CATC + xoff + c];
                As[cc][r] = v;
            } else if (which == 1) {
                if (c < C && (o0 + r) < O)
                    v = w[(size_t)(o0 + r) * twoC + C + c] - w[(size_t)(o0 + r) * twoC + c];
                B0[cc][r] = v;
            } else {
                if (c < C && (o0 + r) < O)
                    v = w[(size_t)(o0 + r) * twoC + c];
                B1[cc][r] = v;
            }
        }
        __syncthreads();
#pragma unroll
        for (int cc = 0; cc < 16; ++cc) {
            float4 a4 = *(const float4*)&As[cc][ty * 4];
            float4 b04 = *(const float4*)&B0[cc][tx * 4];
            float4 b14 = *(const float4*)&B1[cc][tx * 4];
            float aa[4] = {a4.x, a4.y, a4.z, a4.w};
            float b0v[4] = {b04.x, b04.y, b04.z, b04.w};
            float b1v[4] = {b14.x, b14.y, b14.z, b14.w};
#pragma unroll
            for (int i = 0; i < 4; ++i)
#pragma unroll
                for (int j = 0; j < 4; ++j) {
                    acc0[i][j] = fmaf(aa[i], b0v[j], acc0[i][j]);
                    acc1[i][j] = fmaf(aa[i], b1v[j], acc1[i][j]);
                }
        }
        __syncthreads();
    }
#pragma unroll
    for (int i = 0; i < 4; ++i) {
        *(float4*)&g_t[(size_t)(r0 + ty * 4 + i) * O + o0 + tx * 4] =
            make_float4(acc0[i][0], acc0[i][1], acc0[i][2], acc0[i][3]);
        *(float4*)&g_t2[(size_t)(r0 + ty * 4 + i) * O + o0 + tx * 4] =
            make_float4(acc1[i][0], acc1[i][1], acc1[i][2], acc1[i][3]);
    }
}

// ---------------- small GEMM (layer 4 center term, C=128, O=256): float4 loads --------
__global__ void small_gemm(const float* __restrict__ xin, int use_in, int xoff, int C,
                           const float* __restrict__ w, int O, int mode) {
    __shared__ __align__(16) float As[16][68];
    __shared__ __align__(16) float Bs[16][68];
    int r0 = blockIdx.y * 64, o0 = blockIdx.x * 64;
    int tid = threadIdx.x, tx = tid & 15, ty = tid >> 4;
    float acc[4][4] = {};
    int twoC = 2 * C;
    int nch = (C + 15) >> 4;
    for (int ch = 0; ch < nch; ++ch) {
        int c0 = ch * 16;
#pragma unroll
        for (int ii = 0; ii < 2; ++ii) {
            int q4 = tid + ii * 256;
            int which = q4 >> 8, r = (q4 & 255) >> 2, cc4 = q4 & 3;
            int c = c0 + cc4 * 4;
            float4 v;
            if (which == 0) {
                v = *(const float4*)&g_cat[(size_t)(r0 + r) * CATC + xoff + c];
                As[cc4 * 4 + 0][r] = v.x; As[cc4 * 4 + 1][r] = v.y;
                As[cc4 * 4 + 2][r] = v.z; As[cc4 * 4 + 3][r] = v.w;
            } else {
                if (mode) {
                    v = *(const float4*)&w[(size_t)(o0 + r) * twoC + c];
                } else {
                    float4 vh = *(const float4*)&w[(size_t)(o0 + r) * twoC + C + c];
                    float4 vl = *(const float4*)&w[(size_t)(o0 + r) * twoC + c];
                    v = make_float4(vh.x - vl.x, vh.y - vl.y, vh.z - vl.z, vh.w - vl.w);
                }
                Bs[cc4 * 4 + 0][r] = v.x; Bs[cc4 * 4 + 1][r] = v.y;
                Bs[cc4 * 4 + 2][r] = v.z; Bs[cc4 * 4 + 3][r] = v.w;
            }
        }
        __syncthreads();
#pragma unroll
        for (int cc = 0; cc < 16; ++cc) {
            float4 a4 = *(const float4*)&As[cc][ty * 4];
            float4 b4 = *(const float4*)&Bs[cc][tx * 4];
            float aa[4] = {a4.x, a4.y, a4.z, a4.w};
            float bb[4] = {b4.x, b4.y, b4.z, b4.w};
#pragma unroll
            for (int i = 0; i < 4; ++i)
#pragma unroll
                for (int j = 0; j < 4; ++j)
                    acc[i][j] = fmaf(aa[i], bb[j], acc[i][j]);
        }
        __syncthreads();
    }
    float* dst = mode ? g_t2 : g_t;
#pragma unroll
    for (int i = 0; i < 4; ++i) {
        float4 o4 = make_float4(acc[i][0], acc[i][1], acc[i][2], acc[i][3]);
        *(float4*)&dst[(size_t)(r0 + ty * 4 + i) * O + o0 + tx * 4] = o4;
    }
}

// ---------------- neighbor GEMM layer 4 (C=128, O=256): reg prefetch + float4 ---------
__global__ void wx_gemm128(const float* __restrict__ w, int xoff, int O) {
    __shared__ __align__(16) float As[16][132];
    __shared__ __align__(16) float Bs[16][132];
    int r0 = blockIdx.y * 128, o0 = blockIdx.x * 128;
    int tid = threadIdx.x, tx = tid & 15, ty = tid >> 4;
    const int twoC = 256;
    float acc[8][8] = {};
    float4 rg[4];
#pragma unroll
    for (int ii = 0; ii < 4; ++ii) {
        int q4 = tid + ii * 256;
        int which = q4 >> 9, r = (q4 & 511) >> 2, cc4 = q4 & 3;
        rg[ii] = which ? *(const float4*)&w[(size_t)(o0 + r) * twoC + cc4 * 4]
                       : *(const float4*)&g_cat[(size_t)(r0 + r) * CATC + xoff + cc4 * 4];
    }
#pragma unroll 1
    for (int ch = 0; ch < 8; ++ch) {
#pragma unroll
        for (int ii = 0; ii < 4; ++ii) {
            int q4 = tid + ii * 256;
            int which = q4 >> 9, r = (q4 & 511) >> 2, cc4 = q4 & 3;
            float4 v = rg[ii];
            if (which) {
                Bs[cc4 * 4 + 0][r] = v.x; Bs[cc4 * 4 + 1][r] = v.y;
                Bs[cc4 * 4 + 2][r] = v.z; Bs[cc4 * 4 + 3][r] = v.w;
            } else {
                As[cc4 * 4 + 0][r] = v.x; As[cc4 * 4 + 1][r] = v.y;
                As[cc4 * 4 + 2][r] = v.z; As[cc4 * 4 + 3][r] = v.w;
            }
        }
        __syncthreads();
        if (ch + 1 < 8) {
            int c0 = (ch + 1) * 16;
#pragma unroll
            for (int ii = 0; ii < 4; ++ii) {
                int q4 = tid + ii * 256;
                int which = q4 >> 9, r = (q4 & 511) >> 2, cc4 = q4 & 3;
                rg[ii] = which ? *(const float4*)&w[(size_t)(o0 + r) * twoC + c0 + cc4 * 4]
                               : *(const float4*)&g_cat[(size_t)(r0 + r) * CATC + xoff + c0 + cc4 * 4];
            }
        }
#pragma unroll
        for (int cc = 0; cc < 16; ++cc) {
            float4 a0 = *(const float4*)&As[cc][ty * 8];
            float4 a1 = *(const float4*)&As[cc][ty * 8 + 4];
            float4 b0 = *(const float4*)&Bs[cc][tx * 8];
            float4 b1 = *(const float4*)&Bs[cc][tx * 8 + 4];
            float aa[8] = {a0.x, a0.y, a0.z, a0.w, a1.x, a1.y, a1.z, a1.w};
            float bb[8] = {b0.x, b0.y, b0.z, b0.w, b1.x, b1.y, b1.z, b1.w};
#pragma unroll
            for (int i = 0; i < 8; ++i)
#pragma unroll
                for (int j = 0; j < 8; ++j)
                    acc[i][j] = fmaf(aa[i], bb[j], acc[i][j]);
        }
        __syncthreads();
    }
#pragma unroll
    for (int i = 0; i < 8; ++i) {
        size_t base = (size_t)(r0 + ty * 8 + i) * O + o0 + tx * 8;
        *(float4*)&g_t2[base] = make_float4(acc[i][0], acc[i][1], acc[i][2], acc[i][3]);
        *(float4*)&g_t2[base + 4] = make_float4(acc[i][4], acc[i][5], acc[i][6], acc[i][7]);
    }
}

// ---------------- edge epilogue: gather t2 + t, max/sum/sumsq ----------------
__global__ void edge_epilogue(int O, int outoff) {
    __shared__ float redM[16][132];
    __shared__ float redS[16][132];
    __shared__ float redQ[16][132];
    __shared__ int sidx[80];
    int b = blockIdx.z, n0 = blockIdx.y * 4, o0 = blockIdx.x * 128;
    int tid = threadIdx.x, tx = tid & 15, ty = tid >> 4;
    if (tid < 80) sidx[tid] = g_idx[(b * NN + n0 + tid / KK) * KK + tid % KK];
    __syncthreads();
    int p = ty >> 2;
    int nrow = b * NN + n0 + p;
    bool valid = (o0 + tx * 8) < O;
    float tv[8];
    float hv[5][8];
    if (valid) {
        float4 t0 = *(const float4*)&g_t[(size_t)nrow * O + o0 + tx * 8];
        float4 t1 = *(const float4*)&g_t[(size_t)nrow * O + o0 + tx * 8 + 4];
        tv[0]=t0.x; tv[1]=t0.y; tv[2]=t0.z; tv[3]=t0.w;
        tv[4]=t1.x; tv[5]=t1.y; tv[6]=t1.z; tv[7]=t1.w;
#pragma unroll
        for (int i = 0; i < 5; ++i) {
            int nbr = sidx[ty * 5 + i];
            float4 v0 = *(const float4*)&g_t2[(size_t)(b * NN + nbr) * O + o0 + tx * 8];
            float4 v1 = *(const float4*)&g_t2[(size_t)(b * NN + nbr) * O + o0 + tx * 8 + 4];
            hv[i][0]=v0.x; hv[i][1]=v0.y; hv[i][2]=v0.z; hv[i][3]=v0.w;
            hv[i][4]=v1.x; hv[i][5]=v1.y; hv[i][6]=v1.z; hv[i][7]=v1.w;
        }
    } else {
#pragma unroll
        for (int j = 0; j < 8; ++j) tv[j] = 0.f;
#pragma unroll
        for (int i = 0; i < 5; ++i)
#pragma unroll
            for (int j = 0; j < 8; ++j) hv[i][j] = 0.f;
    }
#pragma unroll
    for (int j = 0; j < 8; ++j) {
        float tval = tv[j];
        float mx = -3.402823466e38f, s = 0.f, q = 0.f;
#pragma unroll
        for (int i = 0; i < 5; ++i) {
            float h = hv[i][j] + tval;
            mx = fmaxf(mx, h);
            s += h;
            q += h * h;
        }
        redM[ty][tx * 8 + j] = mx;
        redS[ty][tx * 8 + j] = s;
        redQ[ty][tx * 8 + j] = q;
    }
    __syncthreads();
    for (int t = tid; t < 512; t += 256) {
        int pp = t >> 7, col = t & 127;
        float m0 = fmaxf(redM[pp * 4 + 0][col], redM[pp * 4 + 1][col]);
        float m1 = fmaxf(redM[pp * 4 + 2][col], redM[pp * 4 + 3][col]);
        if (o0 + col < O)
            g_cat[(size_t)(b * NN + n0 + pp) * CATC + outoff + o0 + col] = fmaxf(m0, m1);
    }
    if (tid < 128) {
        float s = 0.f, q = 0.f;
#pragma unroll
        for (int yy = 0; yy < 16; ++yy) { s += redS[yy][tid]; q += redQ[yy][tid]; }
        size_t pidx = (((size_t)b * gridDim.x + blockIdx.x) * (NN / 4) + blockIdx.y) * 128 + tid;
        g_partS[pidx] = s;
        g_partQ[pidx] = q;
    }
}

// ---------------- reduce gather partials -> g_sum/g_sumsq ----------------
__global__ void reduce_conv(int O, int oT) {
    int i = blockIdx.x * 256 + threadIdx.x;
    if (i >= BB * O) return;
    int b = i / O, o = i - b * O;
    int ot = o >> 7, col = o & 127;
    float s = 0.f, q = 0.f;
    for (int ny = 0; ny < NN / 4; ++ny) {
        size_t p = (((size_t)b * oT + ot) * (NN / 4) + ny) * 128 + col;
        s += g_partS[p];
        q += g_partQ[p];
    }
    g_sum[i] = s;
    g_sumsq[i] = q;
}

// ---------------- finalize edge conv: instnorm + leaky, in place ----------------
__global__ void finalize_conv(int O, int outoff) {
    int i = blockIdx.x * 256 + threadIdx.x;
    if (i >= BB * NN * O) return;
    int row = i / O;
    int o = i - row * O;
    int b = row >> 11;
    const float cnt = (float)(NN * KK);
    float mean = g_sum[b * O + o] / cnt;
    float var = fmaxf(g_sumsq[b * O + o] / cnt - mean * mean, 0.f);
    float inv = rsqrtf(var + 1e-5f);
    size_t pidx = (size_t)row * CATC + outoff + o;
    float v = (g_cat[pidx] - mean) * inv;
    g_cat[pidx] = v >= 0.f ? v : 0.2f * v;
}

// ---------------- final conv GEMM: 128x128 tile, reg prefetch + float4 ----------------
__global__ void final_gemm(const float* __restrict__ w5) {
    __shared__ __align__(16) float As[16][132];
    __shared__ __align__(16) float Bs[16][132];
    __shared__ float redS[16][128];
    __shared__ float redQ[16][128];
    int r0 = blockIdx.y * 128, o0 = blockIdx.x * 128;
    int tid = threadIdx.x, tx = tid & 15, ty = tid >> 4;
    float acc[8][8] = {};
    float4 rg[4];
#pragma unroll
    for (int ii = 0; ii < 4; ++ii) {
        int q4 = tid + ii * 256;
        int which = q4 >> 9, r = (q4 & 511) >> 2, cc4 = q4 & 3;
        rg[ii] = which ? *(const float4*)&w5[(size_t)(o0 + r) * 512 + cc4 * 4]
                       : *(const float4*)&g_cat[(size_t)(r0 + r) * CATC + cc4 * 4];
    }
#pragma unroll 1
    for (int ch = 0; ch < 32; ++ch) {
#pragma unroll
        for (int ii = 0; ii < 4; ++ii) {
            int q4 = tid + ii * 256;
            int which = q4 >> 9, r = (q4 & 511) >> 2, cc4 = q4 & 3;
            float4 v = rg[ii];
            if (which) {
                Bs[cc4 * 4 + 0][r] = v.x; Bs[cc4 * 4 + 1][r] = v.y;
                Bs[cc4 * 4 + 2][r] = v.z; Bs[cc4 * 4 + 3][r] = v.w;
            } else {
                As[cc4 * 4 + 0][r] = v.x; As[cc4 * 4 + 1][r] = v.y;
                As[cc4 * 4 + 2][r] = v.z; As[cc4 * 4 + 3][r] = v.w;
            }
        }
        __syncthreads();
        if (ch + 1 < 32) {
            int c0 = (ch + 1) * 16;
#pragma unroll
            for (int ii = 0; ii < 4; ++ii) {
                int q4 = tid + ii * 256;
                int which = q4 >> 9, r = (q4 & 511) >> 2, cc4 = q4 & 3;
                rg[ii] = which ? *(const float4*)&w5[(size_t)(o0 + r) * 512 + c0 + cc4 * 4]
                               : *(const float4*)&g_cat[(size_t)(r0 + r) * CATC + c0 + cc4 * 4];
            }
        }
#pragma unroll
        for (int cc = 0; cc < 16; ++cc) {
            float4 a0 = *(const float4*)&As[cc][ty * 8];
            float4 a1 = *(const float4*)&As[cc][ty * 8 + 4];
            float4 b0 = *(const float4*)&Bs[cc][tx * 8];
            float4 b1 = *(const float4*)&Bs[cc][tx * 8 + 4];
            float aa[8] = {a0.x, a0.y, a0.z, a0.w, a1.x, a1.y, a1.z, a1.w};
            float bb[8] = {b0.x, b0.y, b0.z, b0.w, b1.x, b1.y, b1.z, b1.w};
#pragma unroll
            for (int i = 0; i < 8; ++i)
#pragma unroll
                for (int j = 0; j < 8; ++j)
                    acc[i][j] = fmaf(aa[i], bb[j], acc[i][j]);
        }
        __syncthreads();
    }
    float ls[8] = {}, lq[8] = {};
#pragma unroll
    for (int i = 0; i < 8; ++i) {
        size_t base = (size_t)(r0 + ty * 8 + i) * 512 + o0 + tx * 8;
        *(float4*)&g_h5[base] = make_float4(acc[i][0], acc[i][1], acc[i][2], acc[i][3]);
        *(float4*)&g_h5[base + 4] = make_float4(acc[i][4], acc[i][5], acc[i][6], acc[i][7]);
#pragma unroll
        for (int j = 0; j < 8; ++j) { ls[j] += acc[i][j]; lq[j] += acc[i][j] * acc[i][j]; }
    }
#pragma unroll
    for (int j = 0; j < 8; ++j) { redS[ty][tx * 8 + j] = ls[j]; redQ[ty][tx * 8 + j] = lq[j]; }
    __syncthreads();
    if (tid < 128) {
        float s = 0.f, q = 0.f;
#pragma unroll
        for (int yy = 0; yy < 16; ++yy) { s += redS[yy][tid]; q += redQ[yy][tid]; }
        size_t p = ((size_t)blockIdx.y * 4 + blockIdx.x) * 128 + tid;
        g_partS[p] = s;
        g_partQ[p] = q;
    }
}

__global__ void reduce_final() {
    int i = blockIdx.x * 256 + threadIdx.x;
    if (i >= BB * 512) return;
    int b = i >> 9, o = i & 511;
    int ox = o >> 7, col = o & 127;
    float s = 0.f, q = 0.f;
    for (int yy = 0; yy < 16; ++yy) {
        size_t p = ((size_t)(b * 16 + yy) * 4 + ox) * 128 + col;
        s += g_partS[p];
        q += g_partQ[p];
    }
    g_sum[i] = s;
    g_sumsq[i] = q;
}

// ---------------- final normalize + leaky + transpose to (B,512,N) ----------------
__global__ void finalize_final(float* __restrict__ out) {
    int n = blockIdx.x * blockDim.x + threadIdx.x;
    int o = blockIdx.y, b = blockIdx.z;
    const float cnt = (float)NN;
    float mean = g_sum[b * 512 + o] / cnt;
    float var = fmaxf(g_sumsq[b * 512 + o] / cnt - mean * mean, 0.f);
    float inv = rsqrtf(var + 1e-5f);
    float v = (g_h5[(size_t)(b * NN + n) * 512 + o] - mean) * inv;
    out[((size_t)b * 512 + o) * NN + n] = v >= 0.f ? v : 0.2f * v;
}

// ---------------- host orchestration ----------------
static void run_edge(const float* xin, int use_in, int xoff, int C,
                     const float* w, int O, int outoff) {
    xx_kernel<<<(BB * NN + 255) / 256, 256>>>(xin, use_in, xoff, C);
    dist_gemm<<<dim3(136, 1, BB), 256>>>(xin, use_in, xoff, C);
    topk_kernel<<<dim3(NN, BB), 256>>>();
    if (C == 128 && O == 256) {
        small_gemm<<<dim3((O + 63) / 64, (BB * NN) / 64), 256>>>(xin, use_in, xoff, C, w, O, 0);
        wx_gemm128<<<dim3(O / 128, (BB * NN) / 128), 256>>>(w, xoff, O);
    } else {
        small_gemm2<<<dim3((O + 63) / 64, (BB * NN) / 64), 256>>>(xin, use_in, xoff, C, w, O);
    }
    int oT = (O + 127) / 128;
    edge_epilogue<<<dim3(oT, NN / 4, BB), 256>>>(O, outoff);
    reduce_conv<<<(BB * O + 255) / 256, 256>>>(O, oT);
    finalize_conv<<<(BB * NN * O + 255) / 256, 256>>>(O, outoff);
}

extern "C" void kernel_launch(void* const* d_in, const int* in_sizes, int n_in,
                              void* d_out, int out_size) {
    const float* x  = (const float*)d_in[0];
    const float* w1 = (const float*)d_in[1];
    const float* w2 = (const float*)d_in[2];
    const float* w3 = (const float*)d_in[3];
    const float* w4 = (const float*)d_in[4];
    const float* w5 = (const float*)d_in[5];
    float* out = (float*)d_out;

    run_edge(x, 1, 0,   3,   w1, 64,  0);    // x1 -> cat[:, :,   0: 64]
    run_edge(x, 0, 0,   64,  w2, 64,  64);   // x2 -> cat[:, :,  64:128]
    run_edge(x, 0, 64,  64,  w3, 128, 128);  // x3 -> cat[:, :, 128:256]
    run_edge(x, 0, 128, 128, w4, 256, 256);  // x4 -> cat[:, :, 256:512]

    final_gemm<<<dim3(512 / 128, (BB * NN) / 128), 256>>>(w5);
    reduce_final<<<(BB * 512 + 255) / 256, 256>>>();
    finalize_final<<<dim3(NN / 256, 512, BB), 256>>>(out);
}

// round 16
// speedup vs baseline: 1.0725x; 1.0725x over previous
#include <cuda_runtime.h>
#include <cstdint>

#define BB 8
#define NN 2048
#define KK 20
#define CATC 512

// ---------------- static scratch (no allocations allowed) ----------------
__device__ unsigned g_Dk[(size_t)BB * NN * NN];  // 134 MB pairwise dist as order-preserving keys
__device__ int   g_idx[BB * NN * KK];            // knn indices
__device__ float g_xx[BB * NN];                  // per-point squared norms
__device__ float g_cat[(size_t)BB * NN * CATC];  // concat feature buffer (B,N,512)
__device__ float g_t[(size_t)BB * NN * 256];     // center-term GEMM output (B,N,O)
__device__ float g_t2[(size_t)BB * NN * 256];    // neighbor-term dense GEMM output
__device__ float g_h5[(size_t)BB * NN * 512];    // final conv pre-norm
__device__ float g_partS[(size_t)8 * 2 * 512 * 128]; // per-block partial sums
__device__ float g_partQ[(size_t)8 * 2 * 512 * 128]; // per-block partial sumsq
__device__ float g_sum[BB * 512];
__device__ float g_sumsq[BB * 512];

// order-preserving float -> uint key (strictly monotone, bijective)
__device__ __forceinline__ unsigned f2k(float f) {
    unsigned u = __float_as_uint(f);
    return (u & 0x80000000u) ? ~u : (u | 0x80000000u);
}

// ---------------- xx from input points (layer 1, C=3) ----------------
__global__ void xx_in(const float* __restrict__ xin) {
    int i = blockIdx.x * blockDim.x + threadIdx.x;
    if (i >= BB * NN) return;
    const float* p = xin + (size_t)i * 3;
    float s = 0.f;
    for (int c = 0; c < 3; ++c) s += p[c] * p[c];
    g_xx[i] = s;
}

// ---------------- xx from g_cat (layers 2-4): smem-staged, coalesced loads --------
// Per-row sum order is c-ascending sequential -> bit-identical to scalar version.
__global__ void xx_cat(int xoff, int C) {
    __shared__ float X[64][133];
    int row0 = blockIdx.x * 64;
    int tid = threadIdx.x;
    for (int idx = tid; idx < 64 * C; idx += 256) {
        int r = idx / C, c = idx - r * C;
        X[r][c] = g_cat[(size_t)(row0 + r) * CATC + xoff + c];
    }
    __syncthreads();
    if (tid < 64) {
        float s = 0.f;
        for (int c = 0; c < C; ++c) s += X[tid][c] * X[tid][c];
        g_xx[row0 + tid] = s;
    }
}

// ---------------- distance GEMM (block-triangular + mirror), reg prefetch + float4 ----
__global__ void dist_gemm(const float* __restrict__ xin, int use_in, int xoff, int C) {
    __shared__ __align__(16) float As[16][132];
    __shared__ __align__(16) float Bs[16][132];
    int b = blockIdx.z;
    int t = blockIdx.x;
    int bi = 0;
    while (t >= 16 - bi) { t -= 16 - bi; ++bi; }
    int bj = bi + t;
    int n0 = bi * 128, m0 = bj * 128;
    int tid = threadIdx.x, tx = tid & 15, ty = tid >> 4;
    float acc[8][8] = {};
    int nch = (C + 15) >> 4;
    float4 rg[4];
#pragma unroll
    for (int ii = 0; ii < 4; ++ii) {
        int q4 = tid + ii * 256;
        int which = q4 >> 9, r = (q4 & 511) >> 2, cc4 = q4 & 3;
        int c = cc4 * 4;
        int rowg = b * NN + (which ? m0 : n0) + r;
        if (use_in) {
            float v[4];
#pragma unroll
            for (int e = 0; e < 4; ++e)
                v[e] = (c + e < C) ? xin[(size_t)rowg * 3 + c + e] : 0.f;
            rg[ii] = make_float4(v[0], v[1], v[2], v[3]);
        } else {
            rg[ii] = *(const float4*)&g_cat[(size_t)rowg * CATC + xoff + c];
        }
    }
    for (int ch = 0; ch < nch; ++ch) {
#pragma unroll
        for (int ii = 0; ii < 4; ++ii) {
            int q4 = tid + ii * 256;
            int which = q4 >> 9, r = (q4 & 511) >> 2, cc4 = q4 & 3;
            float4 v = rg[ii];
            if (which) {
                Bs[cc4 * 4 + 0][r] = v.x; Bs[cc4 * 4 + 1][r] = v.y;
                Bs[cc4 * 4 + 2][r] = v.z; Bs[cc4 * 4 + 3][r] = v.w;
            } else {
                As[cc4 * 4 + 0][r] = v.x; As[cc4 * 4 + 1][r] = v.y;
                As[cc4 * 4 + 2][r] = v.z; As[cc4 * 4 + 3][r] = v.w;
            }
        }
        __syncthreads();
        if (ch + 1 < nch) {
            int c0 = (ch + 1) * 16;
#pragma unroll
            for (int ii = 0; ii < 4; ++ii) {
                int q4 = tid + ii * 256;
                int which = q4 >> 9, r = (q4 & 511) >> 2, cc4 = q4 & 3;
                int rowg = b * NN + (which ? m0 : n0) + r;
                rg[ii] = *(const float4*)&g_cat[(size_t)rowg * CATC + xoff + c0 + cc4 * 4];
            }
        }
#pragma unroll
        for (int cc = 0; cc < 16; ++cc) {
            float4 a0 = *(const float4*)&As[cc][ty * 8];
            float4 a1 = *(const float4*)&As[cc][ty * 8 + 4];
            float4 b0 = *(const float4*)&Bs[cc][tx * 8];
            float4 b1 = *(const float4*)&Bs[cc][tx * 8 + 4];
            float aa[8] = {a0.x, a0.y, a0.z, a0.w, a1.x, a1.y, a1.z, a1.w};
            float bb[8] = {b0.x, b0.y, b0.z, b0.w, b1.x, b1.y, b1.z, b1.w};
#pragma unroll
            for (int i = 0; i < 8; ++i)
#pragma unroll
                for (int j = 0; j < 8; ++j)
                    acc[i][j] = fmaf(aa[i], bb[j], acc[i][j]);
        }
        __syncthreads();
    }
    float xn[8], xm[8];
#pragma unroll
    for (int i = 0; i < 8; ++i) xn[i] = g_xx[b * NN + n0 + ty * 8 + i];
#pragma unroll
    for (int j = 0; j < 8; ++j) xm[j] = g_xx[b * NN + m0 + tx * 8 + j];
#pragma unroll
    for (int i = 0; i < 8; ++i) {
        unsigned k[8];
#pragma unroll
        for (int j = 0; j < 8; ++j) k[j] = f2k(2.f * acc[i][j] - xn[i] - xm[j]);
        size_t base = ((size_t)(b * NN + n0 + ty * 8 + i)) * NN + m0 + tx * 8;
        *(uint4*)&g_Dk[base] = make_uint4(k[0], k[1], k[2], k[3]);
        *(uint4*)&g_Dk[base + 4] = make_uint4(k[4], k[5], k[6], k[7]);
    }
    if (bi != bj) {
        unsigned (*Tu)[132] = (unsigned (*)[132])&As[0][0];
#pragma unroll
        for (int g = 0; g < 8; ++g) {
            if ((tx >> 1) == g) {
#pragma unroll
                for (int j = 0; j < 8; ++j)
#pragma unroll
                    for (int i = 0; i < 8; ++i)
                        Tu[(tx & 1) * 8 + j][ty * 8 + i] = f2k(2.f * acc[i][j] - xm[j] - xn[i]);
            }
            __syncthreads();
            for (int q = tid; q < 512; q += 256) {
                int lr = q >> 5;
                int fc = (q & 31) * 4;
                size_t base = ((size_t)(b * NN + m0 + g * 16 + lr)) * NN + n0 + fc;
                *(uint4*)&g_Dk[base] = *(const uint4*)&Tu[lr][fc];
            }
            __syncthreads();
        }
    }
}

// ---------------- top-K=20: radix select, 256 threads, histogram fused into load ------
// Output order identical to 20x iterative argmax with lowest-index tie-break.
__global__ void topk_kernel() {
    __shared__ unsigned keys[NN];
    __shared__ int candA[NN];
    __shared__ int candB[NN];
    __shared__ unsigned hist[256];
    __shared__ unsigned suf[256];
    __shared__ unsigned wtot[8];
    __shared__ int      rmin[256];
    __shared__ unsigned selK[24];
    __shared__ int      selI[24];
    __shared__ int s_rem, s_sel, s_m, s_nc, s_nc2;

    int n = blockIdx.x, b = blockIdx.y;
    int tid = threadIdx.x;
    int lane = tid & 31, w = tid >> 5;
    size_t rowbase = (size_t)(b * NN + n);
    const uint4* row4 = (const uint4*)(g_Dk + rowbase * NN);

    if (tid == 0) { s_rem = KK; s_m = 0; s_nc = 0; }
    hist[tid] = 0u;
    __syncthreads();

    for (int i = tid; i < NN / 4; i += 256) {
        uint4 v = row4[i];
        keys[i * 4 + 0] = v.x;
        keys[i * 4 + 1] = v.y;
        keys[i * 4 + 2] = v.z;
        keys[i * 4 + 3] = v.w;
        atomicAdd(&hist[v.x >> 24], 1u);
        atomicAdd(&hist[v.y >> 24], 1u);
        atomicAdd(&hist[v.z >> 24], 1u);
        atomicAdd(&hist[v.w >> 24], 1u);
    }
    __syncthreads();

    int* cur = candA;
    int* nxt = candB;

#pragma unroll
    for (int p = 0; p < 4; ++p) {
        {
            unsigned v = hist[tid];
#pragma unroll
            for (int d = 1; d < 32; d <<= 1) {
                unsigned o = __shfl_down_sync(0xffffffffu, v, d);
                if (lane + d < 32) v += o;
            }
            if (lane == 0) wtot[w] = v;
            __syncthreads();
            if (w == 0 && lane < 8) {
                unsigned t2 = wtot[lane];
#pragma unroll
                for (int d = 1; d < 8; d <<= 1) {
                    unsigned o = __shfl_down_sync(0xffu, t2, d);
                    if (lane + d < 8) t2 += o;
                }
                wtot[lane] = t2;
            }
            __syncthreads();
            unsigned add = (w < 7) ? wtot[w + 1] : 0u;
            suf[tid] = v + add;
            __syncthreads();
        }
        int rem = s_rem;
        if (suf[tid] >= (unsigned)rem && (tid == 255 || suf[tid + 1] < (unsigned)rem))
            s_sel = tid;
        __syncthreads();
        if (tid == 0) {
            int sel = s_sel;
            s_rem = rem - (int)((sel == 255) ? 0u : suf[sel + 1]);
            s_nc2 = 0;
        }
        __syncthreads();
        unsigned sel = (unsigned)s_sel;
        int shift = 24 - 8 * p;

        if (p == 0) {
            for (int i = tid; i < NN; i += 256) {
                unsigned byte = keys[i] >> 24;
                if (byte > sel) {
                    int pos = atomicAdd(&s_m, 1);
                    selK[pos] = keys[i]; selI[pos] = i;
                } else if (byte == sel) {
                    int pos = atomicAdd(&s_nc2, 1);
                    nxt[pos] = i;
                }
            }
        } else {
            int L = s_nc;
            for (int t2 = tid; t2 < L; t2 += 256) {
                int i = cur[t2];
                unsigned byte = (keys[i] >> shift) & 0xFFu;
                if (byte > sel) {
                    int pos = atomicAdd(&s_m, 1);
                    selK[pos] = keys[i]; selI[pos] = i;
                } else if (byte == sel) {
                    int pos = atomicAdd(&s_nc2, 1);
                    nxt[pos] = i;
                }
            }
        }
        __syncthreads();
        if (tid == 0) s_nc = s_nc2;
        hist[tid] = 0u;
        __syncthreads();
        if (p < 3) {
            int L = s_nc;
            int nshift = 24 - 8 * (p + 1);
            for (int t2 = tid; t2 < L; t2 += 256)
                atomicAdd(&hist[(keys[nxt[t2]] >> nshift) & 0xFFu], 1u);
            __syncthreads();
        }
        { int* tmp = cur; cur = nxt; nxt = tmp; }
    }

    int m = s_m;
    int r = s_rem;
    int L = s_nc;
    int* outp = g_idx + rowbase * KK;
    if (tid == 0) {
        for (int a = 1; a < m; ++a) {
            unsigned kk = selK[a]; int ii = selI[a];
            int bp = a - 1;
            while (bp >= 0 && (selK[bp] < kk || (selK[bp] == kk && selI[bp] > ii))) {
                selK[bp + 1] = selK[bp]; selI[bp + 1] = selI[bp]; --bp;
            }
            selK[bp + 1] = kk; selI[bp + 1] = ii;
        }
        for (int a = 0; a < m; ++a) outp[a] = selI[a];
    }
    __syncthreads();
    for (int round = 0; round < r; ++round) {
        int lm = 0x7FFFFFFF;
        for (int i = tid; i < L; i += 256) lm = min(lm, cur[i]);
        rmin[tid] = lm;
        __syncthreads();
#pragma unroll
        for (int s = 128; s > 0; s >>= 1) {
            if (tid < s) rmin[tid] = min(rmin[tid], rmin[tid + s]);
            __syncthreads();
        }
        int mv = rmin[0];
        if (tid == 0) outp[m + round] = mv;
        for (int i = tid; i < L; i += 256)
            if (cur[i] == mv) cur[i] = 0x7FFFFFFF;
        __syncthreads();
    }
}

// ---------------- merged small GEMM (layers 1-3): g_t and g_t2 from one A tile --------
__global__ void small_gemm2(const float* __restrict__ xin, int use_in, int xoff, int C,
                            const float* __restrict__ w, int O) {
    __shared__ __align__(16) float As[16][68];
    __shared__ __align__(16) float B0[16][68];
    __shared__ __align__(16) float B1[16][68];
    int r0 = blockIdx.y * 64, o0 = blockIdx.x * 64;
    int tid = threadIdx.x, tx = tid & 15, ty = tid >> 4;
    float acc0[4][4] = {};
    float acc1[4][4] = {};
    int twoC = 2 * C;
    int nch = (C + 15) >> 4;
    for (int ch = 0; ch < nch; ++ch) {
        int c0 = ch * 16;
        for (int t = tid; t < 3072; t += 256) {
            int which = t >> 10;
            int r = (t & 1023) >> 4;
            int cc = t & 15;
            int c = c0 + cc;
            float v = 0.f;
            if (which == 0) {
                if (c < C)
                    v = use_in ? xin[(size_t)(r0 + r) * 3 + c]
                               : g_cat[(size_t)(r0 + r) * CATC + xoff + c];
                As[cc][r] = v;
            } else if (which == 1) {
                if (c < C && (o0 + r) < O)
                    v = w[(size_t)(o0 + r) * twoC + C + c] - w[(size_t)(o0 + r) * twoC + c];
                B0[cc][r] = v;
            } else {
                if (c < C && (o0 + r) < O)
                    v = w[(size_t)(o0 + r) * twoC + c];
                B1[cc][r] = v;
            }
        }
        __syncthreads();
#pragma unroll
        for (int cc = 0; cc < 16; ++cc) {
            float4 a4 = *(const float4*)&As[cc][ty * 4];
            float4 b04 = *(const float4*)&B0[cc][tx * 4];
            float4 b14 = *(const float4*)&B1[cc][tx * 4];
            float aa[4] = {a4.x, a4.y, a4.z, a4.w};
            float b0v[4] = {b04.x, b04.y, b04.z, b04.w};
            float b1v[4] = {b14.x, b14.y, b14.z, b14.w};
#pragma unroll
            for (int i = 0; i < 4; ++i)
#pragma unroll
                for (int j = 0; j < 4; ++j) {
                    acc0[i][j] = fmaf(aa[i], b0v[j], acc0[i][j]);
                    acc1[i][j] = fmaf(aa[i], b1v[j], acc1[i][j]);
                }
        }
        __syncthreads();
    }
#pragma unroll
    for (int i = 0; i < 4; ++i) {
        *(float4*)&g_t[(size_t)(r0 + ty * 4 + i) * O + o0 + tx * 4] =
            make_float4(acc0[i][0], acc0[i][1], acc0[i][2], acc0[i][3]);
        *(float4*)&g_t2[(size_t)(r0 + ty * 4 + i) * O + o0 + tx * 4] =
            make_float4(acc1[i][0], acc1[i][1], acc1[i][2], acc1[i][3]);
    }
}

// ---------------- small GEMM (layer 4 center term, C=128, O=256): float4 loads --------
__global__ void small_gemm(const float* __restrict__ xin, int use_in, int xoff, int C,
                           const float* __restrict__ w, int O, int mode) {
    __shared__ __align__(16) float As[16][68];
    __shared__ __align__(16) float Bs[16][68];
    int r0 = blockIdx.y * 64, o0 = blockIdx.x * 64;
    int tid = threadIdx.x, tx = tid & 15, ty = tid >> 4;
    float acc[4][4] = {};
    int twoC = 2 * C;
    int nch = (C + 15) >> 4;
    for (int ch = 0; ch < nch; ++ch) {
        int c0 = ch * 16;
#pragma unroll
        for (int ii = 0; ii < 2; ++ii) {
            int q4 = tid + ii * 256;
            int which = q4 >> 8, r = (q4 & 255) >> 2, cc4 = q4 & 3;
            int c = c0 + cc4 * 4;
            float4 v;
            if (which == 0) {
                v = *(const float4*)&g_cat[(size_t)(r0 + r) * CATC + xoff + c];
                As[cc4 * 4 + 0][r] = v.x; As[cc4 * 4 + 1][r] = v.y;
                As[cc4 * 4 + 2][r] = v.z; As[cc4 * 4 + 3][r] = v.w;
            } else {
                if (mode) {
                    v = *(const float4*)&w[(size_t)(o0 + r) * twoC + c];
                } else {
                    float4 vh = *(const float4*)&w[(size_t)(o0 + r) * twoC + C + c];
                    float4 vl = *(const float4*)&w[(size_t)(o0 + r) * twoC + c];
                    v = make_float4(vh.x - vl.x, vh.y - vl.y, vh.z - vl.z, vh.w - vl.w);
                }
                Bs[cc4 * 4 + 0][r] = v.x; Bs[cc4 * 4 + 1][r] = v.y;
                Bs[cc4 * 4 + 2][r] = v.z; Bs[cc4 * 4 + 3][r] = v.w;
            }
        }
        __syncthreads();
#pragma unroll
        for (int cc = 0; cc < 16; ++cc) {
            float4 a4 = *(const float4*)&As[cc][ty * 4];
            float4 b4 = *(const float4*)&Bs[cc][tx * 4];
            float aa[4] = {a4.x, a4.y, a4.z, a4.w};
            float bb[4] = {b4.x, b4.y, b4.z, b4.w};
#pragma unroll
            for (int i = 0; i < 4; ++i)
#pragma unroll
                for (int j = 0; j < 4; ++j)
                    acc[i][j] = fmaf(aa[i], bb[j], acc[i][j]);
        }
        __syncthreads();
    }
    float* dst = mode ? g_t2 : g_t;
#pragma unroll
    for (int i = 0; i < 4; ++i) {
        float4 o4 = make_float4(acc[i][0], acc[i][1], acc[i][2], acc[i][3]);
        *(float4*)&dst[(size_t)(r0 + ty * 4 + i) * O + o0 + tx * 4] = o4;
    }
}

// ---------------- neighbor GEMM layer 4 (C=128, O=256): reg prefetch + float4 ---------
__global__ void wx_gemm128(const float* __restrict__ w, int xoff, int O) {
    __shared__ __align__(16) float As[16][132];
    __shared__ __align__(16) float Bs[16][132];
    int r0 = blockIdx.y * 128, o0 = blockIdx.x * 128;
    int tid = threadIdx.x, tx = tid & 15, ty = tid >> 4;
    const int twoC = 256;
    float acc[8][8] = {};
    float4 rg[4];
#pragma unroll
    for (int ii = 0; ii < 4; ++ii) {
        int q4 = tid + ii * 256;
        int which = q4 >> 9, r = (q4 & 511) >> 2, cc4 = q4 & 3;
        rg[ii] = which ? *(const float4*)&w[(size_t)(o0 + r) * twoC + cc4 * 4]
                       : *(const float4*)&g_cat[(size_t)(r0 + r) * CATC + xoff + cc4 * 4];
    }
#pragma unroll 1
    for (int ch = 0; ch < 8; ++ch) {
#pragma unroll
        for (int ii = 0; ii < 4; ++ii) {
            int q4 = tid + ii * 256;
            int which = q4 >> 9, r = (q4 & 511) >> 2, cc4 = q4 & 3;
            float4 v = rg[ii];
            if (which) {
                Bs[cc4 * 4 + 0][r] = v.x; Bs[cc4 * 4 + 1][r] = v.y;
                Bs[cc4 * 4 + 2][r] = v.z; Bs[cc4 * 4 + 3][r] = v.w;
            } else {
                As[cc4 * 4 + 0][r] = v.x; As[cc4 * 4 + 1][r] = v.y;
                As[cc4 * 4 + 2][r] = v.z; As[cc4 * 4 + 3][r] = v.w;
            }
        }
        __syncthreads();
        if (ch + 1 < 8) {
            int c0 = (ch + 1) * 16;
#pragma unroll
            for (int ii = 0; ii < 4; ++ii) {
                int q4 = tid + ii * 256;
                int which = q4 >> 9, r = (q4 & 511) >> 2, cc4 = q4 & 3;
                rg[ii] = which ? *(const float4*)&w[(size_t)(o0 + r) * twoC + c0 + cc4 * 4]
                               : *(const float4*)&g_cat[(size_t)(r0 + r) * CATC + xoff + c0 + cc4 * 4];
            }
        }
#pragma unroll
        for (int cc = 0; cc < 16; ++cc) {
            float4 a0 = *(const float4*)&As[cc][ty * 8];
            float4 a1 = *(const float4*)&As[cc][ty * 8 + 4];
            float4 b0 = *(const float4*)&Bs[cc][tx * 8];
            float4 b1 = *(const float4*)&Bs[cc][tx * 8 + 4];
            float aa[8] = {a0.x, a0.y, a0.z, a0.w, a1.x, a1.y, a1.z, a1.w};
            float bb[8] = {b0.x, b0.y, b0.z, b0.w, b1.x, b1.y, b1.z, b1.w};
#pragma unroll
            for (int i = 0; i < 8; ++i)
#pragma unroll
                for (int j = 0; j < 8; ++j)
                    acc[i][j] = fmaf(aa[i], bb[j], acc[i][j]);
        }
        __syncthreads();
    }
#pragma unroll
    for (int i = 0; i < 8; ++i) {
        size_t base = (size_t)(r0 + ty * 8 + i) * O + o0 + tx * 8;
        *(float4*)&g_t2[base] = make_float4(acc[i][0], acc[i][1], acc[i][2], acc[i][3]);
        *(float4*)&g_t2[base + 4] = make_float4(acc[i][4], acc[i][5], acc[i][6], acc[i][7]);
    }
}

// ---------------- edge epilogue: gather t2 + t, max/sum/sumsq ----------------
__global__ void edge_epilogue(int O, int outoff) {
    __shared__ float redM[16][132];
    __shared__ float redS[16][132];
    __shared__ float redQ[16][132];
    __shared__ int sidx[80];
    int b = blockIdx.z, n0 = blockIdx.y * 4, o0 = blockIdx.x * 128;
    int tid = threadIdx.x, tx = tid & 15, ty = tid >> 4;
    if (tid < 80) sidx[tid] = g_idx[(b * NN + n0 + tid / KK) * KK + tid % KK];
    __syncthreads();
    int p = ty >> 2;
    int nrow = b * NN + n0 + p;
    bool valid = (o0 + tx * 8) < O;
    float tv[8];
    float hv[5][8];
    if (valid) {
        float4 t0 = *(const float4*)&g_t[(size_t)nrow * O + o0 + tx * 8];
        float4 t1 = *(const float4*)&g_t[(size_t)nrow * O + o0 + tx * 8 + 4];
        tv[0]=t0.x; tv[1]=t0.y; tv[2]=t0.z; tv[3]=t0.w;
        tv[4]=t1.x; tv[5]=t1.y; tv[6]=t1.z; tv[7]=t1.w;
#pragma unroll
        for (int i = 0; i < 5; ++i) {
            int nbr = sidx[ty * 5 + i];
            float4 v0 = *(const float4*)&g_t2[(size_t)(b * NN + nbr) * O + o0 + tx * 8];
            float4 v1 = *(const float4*)&g_t2[(size_t)(b * NN + nbr) * O + o0 + tx * 8 + 4];
            hv[i][0]=v0.x; hv[i][1]=v0.y; hv[i][2]=v0.z; hv[i][3]=v0.w;
            hv[i][4]=v1.x; hv[i][5]=v1.y; hv[i][6]=v1.z; hv[i][7]=v1.w;
        }
    } else {
#pragma unroll
        for (int j = 0; j < 8; ++j) tv[j] = 0.f;
#pragma unroll
        for (int i = 0; i < 5; ++i)
#pragma unroll
            for (int j = 0; j < 8; ++j) hv[i][j] = 0.f;
    }
#pragma unroll
    for (int j = 0; j < 8; ++j) {
        float tval = tv[j];
        float mx = -3.402823466e38f, s = 0.f, q = 0.f;
#pragma unroll
        for (int i = 0; i < 5; ++i) {
            float h = hv[i][j] + tval;
            mx = fmaxf(mx, h);
            s += h;
            q += h * h;
        }
        redM[ty][tx * 8 + j] = mx;
        redS[ty][tx * 8 + j] = s;
        redQ[ty][tx * 8 + j] = q;
    }
    __syncthreads();
    for (int t = tid; t < 512; t += 256) {
        int pp = t >> 7, col = t & 127;
        float m0 = fmaxf(redM[pp * 4 + 0][col], redM[pp * 4 + 1][col]);
        float m1 = fmaxf(redM[pp * 4 + 2][col], redM[pp * 4 + 3][col]);
        if (o0 + col < O)
            g_cat[(size_t)(b * NN + n0 + pp) * CATC + outoff + o0 + col] = fmaxf(m0, m1);
    }
    if (tid < 128) {
        float s = 0.f, q = 0.f;
#pragma unroll
        for (int yy = 0; yy < 16; ++yy) { s += redS[yy][tid]; q += redQ[yy][tid]; }
        size_t pidx = (((size_t)b * gridDim.x + blockIdx.x) * (NN / 4) + blockIdx.y) * 128 + tid;
        g_partS[pidx] = s;
        g_partQ[pidx] = q;
    }
}

// ---------------- reduce gather partials -> g_sum/g_sumsq ----------------
__global__ void reduce_conv(int O, int oT) {
    int i = blockIdx.x * 256 + threadIdx.x;
    if (i >= BB * O) return;
    int b = i / O, o = i - b * O;
    int ot = o >> 7, col = o & 127;
    float s = 0.f, q = 0.f;
    for (int ny = 0; ny < NN / 4; ++ny) {
        size_t p = (((size_t)b * oT + ot) * (NN / 4) + ny) * 128 + col;
        s += g_partS[p];
        q += g_partQ[p];
    }
    g_sum[i] = s;
    g_sumsq[i] = q;
}

// ---------------- finalize edge conv: instnorm + leaky, in place ----------------
__global__ void finalize_conv(int O, int outoff) {
    int i = blockIdx.x * 256 + threadIdx.x;
    if (i >= BB * NN * O) return;
    int row = i / O;
    int o = i - row * O;
    int b = row >> 11;
    const float cnt = (float)(NN * KK);
    float mean = g_sum[b * O + o] / cnt;
    float var = fmaxf(g_sumsq[b * O + o] / cnt - mean * mean, 0.f);
    float inv = rsqrtf(var + 1e-5f);
    size_t pidx = (size_t)row * CATC + outoff + o;
    float v = (g_cat[pidx] - mean) * inv;
    g_cat[pidx] = v >= 0.f ? v : 0.2f * v;
}

// ---------------- final conv GEMM: 128x128 tile, reg prefetch + float4 ----------------
__global__ void final_gemm(const float* __restrict__ w5) {
    __shared__ __align__(16) float As[16][132];
    __shared__ __align__(16) float Bs[16][132];
    __shared__ float redS[16][128];
    __shared__ float redQ[16][128];
    int r0 = blockIdx.y * 128, o0 = blockIdx.x * 128;
    int tid = threadIdx.x, tx = tid & 15, ty = tid >> 4;
    float acc[8][8] = {};
    float4 rg[4];
#pragma unroll
    for (int ii = 0; ii < 4; ++ii) {
        int q4 = tid + ii * 256;
        int which = q4 >> 9, r = (q4 & 511) >> 2, cc4 = q4 & 3;
        rg[ii] = which ? *(const float4*)&w5[(size_t)(o0 + r) * 512 + cc4 * 4]
                       : *(const float4*)&g_cat[(size_t)(r0 + r) * CATC + cc4 * 4];
    }
#pragma unroll 1
    for (int ch = 0; ch < 32; ++ch) {
#pragma unroll
        for (int ii = 0; ii < 4; ++ii) {
            int q4 = tid + ii * 256;
            int which = q4 >> 9, r = (q4 & 511) >> 2, cc4 = q4 & 3;
            float4 v = rg[ii];
            if (which) {
                Bs[cc4 * 4 + 0][r] = v.x; Bs[cc4 * 4 + 1][r] = v.y;
                Bs[cc4 * 4 + 2][r] = v.z; Bs[cc4 * 4 + 3][r] = v.w;
            } else {
                As[cc4 * 4 + 0][r] = v.x; As[cc4 * 4 + 1][r] = v.y;
                As[cc4 * 4 + 2][r] = v.z; As[cc4 * 4 + 3][r] = v.w;
            }
        }
        __syncthreads();
        if (ch + 1 < 32) {
            int c0 = (ch + 1) * 16;
#pragma unroll
            for (int ii = 0; ii < 4; ++ii) {
                int q4 = tid + ii * 256;
                int which = q4 >> 9, r = (q4 & 511) >> 2, cc4 = q4 & 3;
                rg[ii] = which ? *(const float4*)&w5[(size_t)(o0 + r) * 512 + c0 + cc4 * 4]
                               : *(const float4*)&g_cat[(size_t)(r0 + r) * CATC + c0 + cc4 * 4];
            }
        }
#pragma unroll
        for (int cc = 0; cc < 16; ++cc) {
            float4 a0 = *(const float4*)&As[cc][ty * 8];
            float4 a1 = *(const float4*)&As[cc][ty * 8 + 4];
            float4 b0 = *(const float4*)&Bs[cc][tx * 8];
            float4 b1 = *(const float4*)&Bs[cc][tx * 8 + 4];
            float aa[8] = {a0.x, a0.y, a0.z, a0.w, a1.x, a1.y, a1.z, a1.w};
            float bb[8] = {b0.x, b0.y, b0.z, b0.w, b1.x, b1.y, b1.z, b1.w};
#pragma unroll
            for (int i = 0; i < 8; ++i)
#pragma unroll
                for (int j = 0; j < 8; ++j)
                    acc[i][j] = fmaf(aa[i], bb[j], acc[i][j]);
        }
        __syncthreads();
    }
    float ls[8] = {}, lq[8] = {};
#pragma unroll
    for (int i = 0; i < 8; ++i) {
        size_t base = (size_t)(r0 + ty * 8 + i) * 512 + o0 + tx * 8;
        *(float4*)&g_h5[base] = make_float4(acc[i][0], acc[i][1], acc[i][2], acc[i][3]);
        *(float4*)&g_h5[base + 4] = make_float4(acc[i][4], acc[i][5], acc[i][6], acc[i][7]);
#pragma unroll
        for (int j = 0; j < 8; ++j) { ls[j] += acc[i][j]; lq[j] += acc[i][j] * acc[i][j]; }
    }
#pragma unroll
    for (int j = 0; j < 8; ++j) { redS[ty][tx * 8 + j] = ls[j]; redQ[ty][tx * 8 + j] = lq[j]; }
    __syncthreads();
    if (tid < 128) {
        float s = 0.f, q = 0.f;
#pragma unroll
        for (int yy = 0; yy < 16; ++yy) { s += redS[yy][tid]; q += redQ[yy][tid]; }
        size_t p = ((size_t)blockIdx.y * 4 + blockIdx.x) * 128 + tid;
        g_partS[p] = s;
        g_partQ[p] = q;
    }
}

__global__ void reduce_final() {
    int i = blockIdx.x * 256 + threadIdx.x;
    if (i >= BB * 512) return;
    int b = i >> 9, o = i & 511;
    int ox = o >> 7, col = o & 127;
    float s = 0.f, q = 0.f;
    for (int yy = 0; yy < 16; ++yy) {
        size_t p = ((size_t)(b * 16 + yy) * 4 + ox) * 128 + col;
        s += g_partS[p];
        q += g_partQ[p];
    }
    g_sum[i] = s;
    g_sumsq[i] = q;
}

// ---------------- final normalize + leaky + transpose to (B,512,N) ----------------
// 32x32 smem-tiled transpose: both the h5 read and the out write are coalesced
// (the old version had a 32x sector-amplified strided read of g_h5).
__global__ void finalize_final(float* __restrict__ out) {
    __shared__ float S[32][33];
    int n0 = blockIdx.x * 32, o0 = blockIdx.y * 32, b = blockIdx.z;
    int tx = threadIdx.x;        // 0..31
    int ty = threadIdx.y;        // 0..7
    const float cnt = (float)NN;
    // per-thread column params for o = o0 + tx (same formula/bits as before)
    float mean, inv;
    {
        int o = o0 + tx;
        mean = g_sum[b * 512 + o] / cnt;
        float var = fmaxf(g_sumsq[b * 512 + o] / cnt - mean * mean, 0.f);
        inv = rsqrtf(var + 1e-5f);
    }
#pragma unroll
    for (int ph = 0; ph < 4; ++ph) {
        int nl = ty + ph * 8;
        float v = (g_h5[(size_t)(b * NN + n0 + nl) * 512 + o0 + tx] - mean) * inv;
        v = v >= 0.f ? v : 0.2f * v;
        S[tx][nl] = v;           // S[o_local][n_local]
    }
    __syncthreads();
#pragma unroll
    for (int ph = 0; ph < 4; ++ph) {
        int ol = ty + ph * 8;
        out[((size_t)b * 512 + o0 + ol) * NN + n0 + tx] = S[ol][tx];
    }
}

// ---------------- host orchestration ----------------
static void run_edge(const float* xin, int use_in, int xoff, int C,
                     const float* w, int O, int outoff) {
    if (use_in)
        xx_in<<<(BB * NN + 255) / 256, 256>>>(xin);
    else
        xx_cat<<<BB * NN / 64, 256>>>(xoff, C);
    dist_gemm<<<dim3(136, 1, BB), 256>>>(xin, use_in, xoff, C);
    topk_kernel<<<dim3(NN, BB), 256>>>();
    if (C == 128 && O == 256) {
        small_gemm<<<dim3((O + 63) / 64, (BB * NN) / 64), 256>>>(xin, use_in, xoff, C, w, O, 0);
        wx_gemm128<<<dim3(O / 128, (BB * NN) / 128), 256>>>(w, xoff, O);
    } else {
        small_gemm2<<<dim3((O + 63) / 64, (BB * NN) / 64), 256>>>(xin, use_in, xoff, C, w, O);
    }
    int oT = (O + 127) / 128;
    edge_epilogue<<<dim3(oT, NN / 4, BB), 256>>>(O, outoff);
    reduce_conv<<<(BB * O + 255) / 256, 256>>>(O, oT);
    finalize_conv<<<(BB * NN * O + 255) / 256, 256>>>(O, outoff);
}

extern "C" void kernel_launch(void* const* d_in, const int* in_sizes, int n_in,
                              void* d_out, int out_size) {
    const float* x  = (const float*)d_in[0];
    const float* w1 = (const float*)d_in[1];
    const float* w2 = (const float*)d_in[2];
    const float* w3 = (const float*)d_in[3];
    const float* w4 = (const float*)d_in[4];
    const float* w5 = (const float*)d_in[5];
    float* out = (float*)d_out;

    run_edge(x, 1, 0,   3,   w1, 64,  0);    // x1 -> cat[:, :,   0: 64]
    run_edge(x, 0, 0,   64,  w2, 64,  64);   // x2 -> cat[:, :,  64:128]
    run_edge(x, 0, 64,  64,  w3, 128, 128);  // x3 -> cat[:, :, 128:256]
    run_edge(x, 0, 128, 128, w4, 256, 256);  // x4 -> cat[:, :, 256:512]

    final_gemm<<<dim3(512 / 128, (BB * NN) / 128), 256>>>(w5);
    reduce_final<<<(BB * 512 + 255) / 256, 256>>>();
    finalize_final<<<dim3(NN / 32, 512 / 32, BB), dim3(32, 8)>>>(out);
}

// round 17
// speedup vs baseline: 1.0740x; 1.0014x over previous
#include <cuda_runtime.h>
#include <cstdint>

#define BB 8
#define NN 2048
#define KK 20
#define CATC 512

// ---------------- static scratch (no allocations allowed) ----------------
__device__ unsigned g_Dk[(size_t)BB * NN * NN];  // 134 MB pairwise dist as order-preserving keys
__device__ int   g_idx[BB * NN * KK];            // knn indices
__device__ float g_xx[BB * NN];                  // per-point squared norms
__device__ float g_cat[(size_t)BB * NN * CATC];  // concat feature buffer (B,N,512)
__device__ float g_t[(size_t)BB * NN * 256];     // center-term GEMM output (B,N,O)
__device__ float g_t2[(size_t)BB * NN * 256];    // neighbor-term dense GEMM output
__device__ float g_h5[(size_t)BB * NN * 512];    // final conv pre-norm
__device__ float g_partS[(size_t)8 * 2 * 512 * 128]; // per-block partial sums
__device__ float g_partQ[(size_t)8 * 2 * 512 * 128]; // per-block partial sumsq
__device__ float g_sum[BB * 512];
__device__ float g_sumsq[BB * 512];

// order-preserving float -> uint key (strictly monotone, bijective)
__device__ __forceinline__ unsigned f2k(float f) {
    unsigned u = __float_as_uint(f);
    return (u & 0x80000000u) ? ~u : (u | 0x80000000u);
}

// ---------------- xx from input points (layer 1, C=3) ----------------
__global__ void xx_in(const float* __restrict__ xin) {
    int i = blockIdx.x * blockDim.x + threadIdx.x;
    if (i >= BB * NN) return;
    const float* p = xin + (size_t)i * 3;
    float s = 0.f;
    for (int c = 0; c < 3; ++c) s += p[c] * p[c];
    g_xx[i] = s;
}

// ---------------- distance GEMM (block-triangular + mirror), reg prefetch + float4 ----
__global__ void dist_gemm(const float* __restrict__ xin, int use_in, int xoff, int C) {
    __shared__ __align__(16) float As[16][132];
    __shared__ __align__(16) float Bs[16][132];
    int b = blockIdx.z;
    int t = blockIdx.x;
    int bi = 0;
    while (t >= 16 - bi) { t -= 16 - bi; ++bi; }
    int bj = bi + t;
    int n0 = bi * 128, m0 = bj * 128;
    int tid = threadIdx.x, tx = tid & 15, ty = tid >> 4;
    float acc[8][8] = {};
    int nch = (C + 15) >> 4;
    float4 rg[4];
#pragma unroll
    for (int ii = 0; ii < 4; ++ii) {
        int q4 = tid + ii * 256;
        int which = q4 >> 9, r = (q4 & 511) >> 2, cc4 = q4 & 3;
        int c = cc4 * 4;
        int rowg = b * NN + (which ? m0 : n0) + r;
        if (use_in) {
            float v[4];
#pragma unroll
            for (int e = 0; e < 4; ++e)
                v[e] = (c + e < C) ? xin[(size_t)rowg * 3 + c + e] : 0.f;
            rg[ii] = make_float4(v[0], v[1], v[2], v[3]);
        } else {
            rg[ii] = *(const float4*)&g_cat[(size_t)rowg * CATC + xoff + c];
        }
    }
    for (int ch = 0; ch < nch; ++ch) {
#pragma unroll
        for (int ii = 0; ii < 4; ++ii) {
            int q4 = tid + ii * 256;
            int which = q4 >> 9, r = (q4 & 511) >> 2, cc4 = q4 & 3;
            float4 v = rg[ii];
            if (which) {
                Bs[cc4 * 4 + 0][r] = v.x; Bs[cc4 * 4 + 1][r] = v.y;
                Bs[cc4 * 4 + 2][r] = v.z; Bs[cc4 * 4 + 3][r] = v.w;
            } else {
                As[cc4 * 4 + 0][r] = v.x; As[cc4 * 4 + 1][r] = v.y;
                As[cc4 * 4 + 2][r] = v.z; As[cc4 * 4 + 3][r] = v.w;
            }
        }
        __syncthreads();
        if (ch + 1 < nch) {
            int c0 = (ch + 1) * 16;
#pragma unroll
            for (int ii = 0; ii < 4; ++ii) {
                int q4 = tid + ii * 256;
                int which = q4 >> 9, r = (q4 & 511) >> 2, cc4 = q4 & 3;
                int rowg = b * NN + (which ? m0 : n0) + r;
                rg[ii] = *(const float4*)&g_cat[(size_t)rowg * CATC + xoff + c0 + cc4 * 4];
            }
        }
#pragma unroll
        for (int cc = 0; cc < 16; ++cc) {
            float4 a0 = *(const float4*)&As[cc][ty * 8];
            float4 a1 = *(const float4*)&As[cc][ty * 8 + 4];
            float4 b0 = *(const float4*)&Bs[cc][tx * 8];
            float4 b1 = *(const float4*)&Bs[cc][tx * 8 + 4];
            float aa[8] = {a0.x, a0.y, a0.z, a0.w, a1.x, a1.y, a1.z, a1.w};
            float bb[8] = {b0.x, b0.y, b0.z, b0.w, b1.x, b1.y, b1.z, b1.w};
#pragma unroll
            for (int i = 0; i < 8; ++i)
#pragma unroll
                for (int j = 0; j < 8; ++j)
                    acc[i][j] = fmaf(aa[i], bb[j], acc[i][j]);
        }
        __syncthreads();
    }
    float xn[8], xm[8];
#pragma unroll
    for (int i = 0; i < 8; ++i) xn[i] = g_xx[b * NN + n0 + ty * 8 + i];
#pragma unroll
    for (int j = 0; j < 8; ++j) xm[j] = g_xx[b * NN + m0 + tx * 8 + j];
#pragma unroll
    for (int i = 0; i < 8; ++i) {
        unsigned k[8];
#pragma unroll
        for (int j = 0; j < 8; ++j) k[j] = f2k(2.f * acc[i][j] - xn[i] - xm[j]);
        size_t base = ((size_t)(b * NN + n0 + ty * 8 + i)) * NN + m0 + tx * 8;
        *(uint4*)&g_Dk[base] = make_uint4(k[0], k[1], k[2], k[3]);
        *(uint4*)&g_Dk[base + 4] = make_uint4(k[4], k[5], k[6], k[7]);
    }
    if (bi != bj) {
        unsigned (*Tu)[132] = (unsigned (*)[132])&As[0][0];
#pragma unroll
        for (int g = 0; g < 8; ++g) {
            if ((tx >> 1) == g) {
#pragma unroll
                for (int j = 0; j < 8; ++j)
#pragma unroll
                    for (int i = 0; i < 8; ++i)
                        Tu[(tx & 1) * 8 + j][ty * 8 + i] = f2k(2.f * acc[i][j] - xm[j] - xn[i]);
            }
            __syncthreads();
            for (int q = tid; q < 512; q += 256) {
                int lr = q >> 5;
                int fc = (q & 31) * 4;
                size_t base = ((size_t)(b * NN + m0 + g * 16 + lr)) * NN + n0 + fc;
                *(uint4*)&g_Dk[base] = *(const uint4*)&Tu[lr][fc];
            }
            __syncthreads();
        }
    }
}

// ---------------- top-K=20: radix select, 256 threads, histogram fused into load ------
__global__ void topk_kernel() {
    __shared__ unsigned keys[NN];
    __shared__ int candA[NN];
    __shared__ int candB[NN];
    __shared__ unsigned hist[256];
    __shared__ unsigned suf[256];
    __shared__ unsigned wtot[8];
    __shared__ int      rmin[256];
    __shared__ unsigned selK[24];
    __shared__ int      selI[24];
    __shared__ int s_rem, s_sel, s_m, s_nc, s_nc2;

    int n = blockIdx.x, b = blockIdx.y;
    int tid = threadIdx.x;
    int lane = tid & 31, w = tid >> 5;
    size_t rowbase = (size_t)(b * NN + n);
    const uint4* row4 = (const uint4*)(g_Dk + rowbase * NN);

    if (tid == 0) { s_rem = KK; s_m = 0; s_nc = 0; }
    hist[tid] = 0u;
    __syncthreads();

    for (int i = tid; i < NN / 4; i += 256) {
        uint4 v = row4[i];
        keys[i * 4 + 0] = v.x;
        keys[i * 4 + 1] = v.y;
        keys[i * 4 + 2] = v.z;
        keys[i * 4 + 3] = v.w;
        atomicAdd(&hist[v.x >> 24], 1u);
        atomicAdd(&hist[v.y >> 24], 1u);
        atomicAdd(&hist[v.z >> 24], 1u);
        atomicAdd(&hist[v.w >> 24], 1u);
    }
    __syncthreads();

    int* cur = candA;
    int* nxt = candB;

#pragma unroll
    for (int p = 0; p < 4; ++p) {
        {
            unsigned v = hist[tid];
#pragma unroll
            for (int d = 1; d < 32; d <<= 1) {
                unsigned o = __shfl_down_sync(0xffffffffu, v, d);
                if (lane + d < 32) v += o;
            }
            if (lane == 0) wtot[w] = v;
            __syncthreads();
            if (w == 0 && lane < 8) {
                unsigned t2 = wtot[lane];
#pragma unroll
                for (int d = 1; d < 8; d <<= 1) {
                    unsigned o = __shfl_down_sync(0xffu, t2, d);
                    if (lane + d < 8) t2 += o;
                }
                wtot[lane] = t2;
            }
            __syncthreads();
            unsigned add = (w < 7) ? wtot[w + 1] : 0u;
            suf[tid] = v + add;
            __syncthreads();
        }
        int rem = s_rem;
        if (suf[tid] >= (unsigned)rem && (tid == 255 || suf[tid + 1] < (unsigned)rem))
            s_sel = tid;
        __syncthreads();
        if (tid == 0) {
            int sel = s_sel;
            s_rem = rem - (int)((sel == 255) ? 0u : suf[sel + 1]);
            s_nc2 = 0;
        }
        __syncthreads();
        unsigned sel = (unsigned)s_sel;
        int shift = 24 - 8 * p;

        if (p == 0) {
            for (int i = tid; i < NN; i += 256) {
                unsigned byte = keys[i] >> 24;
                if (byte > sel) {
                    int pos = atomicAdd(&s_m, 1);
                    selK[pos] = keys[i]; selI[pos] = i;
                } else if (byte == sel) {
                    int pos = atomicAdd(&s_nc2, 1);
                    nxt[pos] = i;
                }
            }
        } else {
            int L = s_nc;
            for (int t2 = tid; t2 < L; t2 += 256) {
                int i = cur[t2];
                unsigned byte = (keys[i] >> shift) & 0xFFu;
                if (byte > sel) {
                    int pos = atomicAdd(&s_m, 1);
                    selK[pos] = keys[i]; selI[pos] = i;
                } else if (byte == sel) {
                    int pos = atomicAdd(&s_nc2, 1);
                    nxt[pos] = i;
                }
            }
        }
        __syncthreads();
        if (tid == 0) s_nc = s_nc2;
        hist[tid] = 0u;
        __syncthreads();
        if (p < 3) {
            int L = s_nc;
            int nshift = 24 - 8 * (p + 1);
            for (int t2 = tid; t2 < L; t2 += 256)
                atomicAdd(&hist[(keys[nxt[t2]] >> nshift) & 0xFFu], 1u);
            __syncthreads();
        }
        { int* tmp = cur; cur = nxt; nxt = tmp; }
    }

    int m = s_m;
    int r = s_rem;
    int L = s_nc;
    int* outp = g_idx + rowbase * KK;
    if (tid == 0) {
        for (int a = 1; a < m; ++a) {
            unsigned kk = selK[a]; int ii = selI[a];
            int bp = a - 1;
            while (bp >= 0 && (selK[bp] < kk || (selK[bp] == kk && selI[bp] > ii))) {
                selK[bp + 1] = selK[bp]; selI[bp + 1] = selI[bp]; --bp;
            }
            selK[bp + 1] = kk; selI[bp + 1] = ii;
        }
        for (int a = 0; a < m; ++a) outp[a] = selI[a];
    }
    __syncthreads();
    for (int round = 0; round < r; ++round) {
        int lm = 0x7FFFFFFF;
        for (int i = tid; i < L; i += 256) lm = min(lm, cur[i]);
        rmin[tid] = lm;
        __syncthreads();
#pragma unroll
        for (int s = 128; s > 0; s >>= 1) {
            if (tid < s) rmin[tid] = min(rmin[tid], rmin[tid + s]);
            __syncthreads();
        }
        int mv = rmin[0];
        if (tid == 0) outp[m + round] = mv;
        for (int i = tid; i < L; i += 256)
            if (cur[i] == mv) cur[i] = 0x7FFFFFFF;
        __syncthreads();
    }
}

// ---------------- merged small GEMM (layers 1-3): g_t and g_t2 from one A tile --------
__global__ void small_gemm2(const float* __restrict__ xin, int use_in, int xoff, int C,
                            const float* __restrict__ w, int O) {
    __shared__ __align__(16) float As[16][68];
    __shared__ __align__(16) float B0[16][68];
    __shared__ __align__(16) float B1[16][68];
    int r0 = blockIdx.y * 64, o0 = blockIdx.x * 64;
    int tid = threadIdx.x, tx = tid & 15, ty = tid >> 4;
    float acc0[4][4] = {};
    float acc1[4][4] = {};
    int twoC = 2 * C;
    int nch = (C + 15) >> 4;
    for (int ch = 0; ch < nch; ++ch) {
        int c0 = ch * 16;
        for (int t = tid; t < 3072; t += 256) {
            int which = t >> 10;
            int r = (t & 1023) >> 4;
            int cc = t & 15;
            int c = c0 + cc;
            float v = 0.f;
            if (which == 0) {
                if (c < C)
                    v = use_in ? xin[(size_t)(r0 + r) * 3 + c]
                               : g_cat[(size_t)(r0 + r) * CATC + xoff + c];
                As[cc][r] = v;
            } else if (which == 1) {
                if (c < C && (o0 + r) < O)
                    v = w[(size_t)(o0 + r) * twoC + C + c] - w[(size_t)(o0 + r) * twoC + c];
                B0[cc][r] = v;
            } else {
                if (c < C && (o0 + r) < O)
                    v = w[(size_t)(o0 + r) * twoC + c];
                B1[cc][r] = v;
            }
        }
        __syncthreads();
#pragma unroll
        for (int cc = 0; cc < 16; ++cc) {
            float4 a4 = *(const float4*)&As[cc][ty * 4];
            float4 b04 = *(const float4*)&B0[cc][tx * 4];
            float4 b14 = *(const float4*)&B1[cc][tx * 4];
            float aa[4] = {a4.x, a4.y, a4.z, a4.w};
            float b0v[4] = {b04.x, b04.y, b04.z, b04.w};
            float b1v[4] = {b14.x, b14.y, b14.z, b14.w};
#pragma unroll
            for (int i = 0; i < 4; ++i)
#pragma unroll
                for (int j = 0; j < 4; ++j) {
                    acc0[i][j] = fmaf(aa[i], b0v[j], acc0[i][j]);
                    acc1[i][j] = fmaf(aa[i], b1v[j], acc1[i][j]);
                }
        }
        __syncthreads();
    }
#pragma unroll
    for (int i = 0; i < 4; ++i) {
        *(float4*)&g_t[(size_t)(r0 + ty * 4 + i) * O + o0 + tx * 4] =
            make_float4(acc0[i][0], acc0[i][1], acc0[i][2], acc0[i][3]);
        *(float4*)&g_t2[(size_t)(r0 + ty * 4 + i) * O + o0 + tx * 4] =
            make_float4(acc1[i][0], acc1[i][1], acc1[i][2], acc1[i][3]);
    }
}

// ---------------- small GEMM (layer 4 center term, C=128, O=256): float4 loads --------
__global__ void small_gemm(const float* __restrict__ xin, int use_in, int xoff, int C,
                           const float* __restrict__ w, int O, int mode) {
    __shared__ __align__(16) float As[16][68];
    __shared__ __align__(16) float Bs[16][68];
    int r0 = blockIdx.y * 64, o0 = blockIdx.x * 64;
    int tid = threadIdx.x, tx = tid & 15, ty = tid >> 4;
    float acc[4][4] = {};
    int twoC = 2 * C;
    int nch = (C + 15) >> 4;
    for (int ch = 0; ch < nch; ++ch) {
        int c0 = ch * 16;
#pragma unroll
        for (int ii = 0; ii < 2; ++ii) {
            int q4 = tid + ii * 256;
            int which = q4 >> 8, r = (q4 & 255) >> 2, cc4 = q4 & 3;
            int c = c0 + cc4 * 4;
            float4 v;
            if (which == 0) {
                v = *(const float4*)&g_cat[(size_t)(r0 + r) * CATC + xoff + c];
                As[cc4 * 4 + 0][r] = v.x; As[cc4 * 4 + 1][r] = v.y;
                As[cc4 * 4 + 2][r] = v.z; As[cc4 * 4 + 3][r] = v.w;
            } else {
                if (mode) {
                    v = *(const float4*)&w[(size_t)(o0 + r) * twoC + c];
                } else {
                    float4 vh = *(const float4*)&w[(size_t)(o0 + r) * twoC + C + c];
                    float4 vl = *(const float4*)&w[(size_t)(o0 + r) * twoC + c];
                    v = make_float4(vh.x - vl.x, vh.y - vl.y, vh.z - vl.z, vh.w - vl.w);
                }
                Bs[cc4 * 4 + 0][r] = v.x; Bs[cc4 * 4 + 1][r] = v.y;
                Bs[cc4 * 4 + 2][r] = v.z; Bs[cc4 * 4 + 3][r] = v.w;
            }
        }
        __syncthreads();
#pragma unroll
        for (int cc = 0; cc < 16; ++cc) {
            float4 a4 = *(const float4*)&As[cc][ty * 4];
            float4 b4 = *(const float4*)&Bs[cc][tx * 4];
            float aa[4] = {a4.x, a4.y, a4.z, a4.w};
            float bb[4] = {b4.x, b4.y, b4.z, b4.w};
#pragma unroll
            for (int i = 0; i < 4; ++i)
#pragma unroll
                for (int j = 0; j < 4; ++j)
                    acc[i][j] = fmaf(aa[i], bb[j], acc[i][j]);
        }
        __syncthreads();
    }
    float* dst = mode ? g_t2 : g_t;
#pragma unroll
    for (int i = 0; i < 4; ++i) {
        float4 o4 = make_float4(acc[i][0], acc[i][1], acc[i][2], acc[i][3]);
        *(float4*)&dst[(size_t)(r0 + ty * 4 + i) * O + o0 + tx * 4] = o4;
    }
}

// ---------------- neighbor GEMM layer 4 (C=128, O=256): reg prefetch + float4 ---------
__global__ void wx_gemm128(const float* __restrict__ w, int xoff, int O) {
    __shared__ __align__(16) float As[16][132];
    __shared__ __align__(16) float Bs[16][132];
    int r0 = blockIdx.y * 128, o0 = blockIdx.x * 128;
    int tid = threadIdx.x, tx = tid & 15, ty = tid >> 4;
    const int twoC = 256;
    float acc[8][8] = {};
    float4 rg[4];
#pragma unroll
    for (int ii = 0; ii < 4; ++ii) {
        int q4 = tid + ii * 256;
        int which = q4 >> 9, r = (q4 & 511) >> 2, cc4 = q4 & 3;
        rg[ii] = which ? *(const float4*)&w[(size_t)(o0 + r) * twoC + cc4 * 4]
                       : *(const float4*)&g_cat[(size_t)(r0 + r) * CATC + xoff + cc4 * 4];
    }
#pragma unroll 1
    for (int ch = 0; ch < 8; ++ch) {
#pragma unroll
        for (int ii = 0; ii < 4; ++ii) {
            int q4 = tid + ii * 256;
            int which = q4 >> 9, r = (q4 & 511) >> 2, cc4 = q4 & 3;
            float4 v = rg[ii];
            if (which) {
                Bs[cc4 * 4 + 0][r] = v.x; Bs[cc4 * 4 + 1][r] = v.y;
                Bs[cc4 * 4 + 2][r] = v.z; Bs[cc4 * 4 + 3][r] = v.w;
            } else {
                As[cc4 * 4 + 0][r] = v.x; As[cc4 * 4 + 1][r] = v.y;
                As[cc4 * 4 + 2][r] = v.z; As[cc4 * 4 + 3][r] = v.w;
            }
        }
        __syncthreads();
        if (ch + 1 < 8) {
            int c0 = (ch + 1) * 16;
#pragma unroll
            for (int ii = 0; ii < 4; ++ii) {
                int q4 = tid + ii * 256;
                int which = q4 >> 9, r = (q4 & 511) >> 2, cc4 = q4 & 3;
                rg[ii] = which ? *(const float4*)&w[(size_t)(o0 + r) * twoC + c0 + cc4 * 4]
                               : *(const float4*)&g_cat[(size_t)(r0 + r) * CATC + xoff + c0 + cc4 * 4];
            }
        }
#pragma unroll
        for (int cc = 0; cc < 16; ++cc) {
            float4 a0 = *(const float4*)&As[cc][ty * 8];
            float4 a1 = *(const float4*)&As[cc][ty * 8 + 4];
            float4 b0 = *(const float4*)&Bs[cc][tx * 8];
            float4 b1 = *(const float4*)&Bs[cc][tx * 8 + 4];
            float aa[8] = {a0.x, a0.y, a0.z, a0.w, a1.x, a1.y, a1.z, a1.w};
            float bb[8] = {b0.x, b0.y, b0.z, b0.w, b1.x, b1.y, b1.z, b1.w};
#pragma unroll
            for (int i = 0; i < 8; ++i)
#pragma unroll
                for (int j = 0; j < 8; ++j)
                    acc[i][j] = fmaf(aa[i], bb[j], acc[i][j]);
        }
        __syncthreads();
    }
#pragma unroll
    for (int i = 0; i < 8; ++i) {
        size_t base = (size_t)(r0 + ty * 8 + i) * O + o0 + tx * 8;
        *(float4*)&g_t2[base] = make_float4(acc[i][0], acc[i][1], acc[i][2], acc[i][3]);
        *(float4*)&g_t2[base + 4] = make_float4(acc[i][4], acc[i][5], acc[i][6], acc[i][7]);
    }
}

// ---------------- edge epilogue: gather t2 + t, max/sum/sumsq ----------------
__global__ void edge_epilogue(int O, int outoff) {
    __shared__ float redM[16][132];
    __shared__ float redS[16][132];
    __shared__ float redQ[16][132];
    __shared__ int sidx[80];
    int b = blockIdx.z, n0 = blockIdx.y * 4, o0 = blockIdx.x * 128;
    int tid = threadIdx.x, tx = tid & 15, ty = tid >> 4;
    if (tid < 80) sidx[tid] = g_idx[(b * NN + n0 + tid / KK) * KK + tid % KK];
    __syncthreads();
    int p = ty >> 2;
    int nrow = b * NN + n0 + p;
    bool valid = (o0 + tx * 8) < O;
    float tv[8];
    float hv[5][8];
    if (valid) {
        float4 t0 = *(const float4*)&g_t[(size_t)nrow * O + o0 + tx * 8];
        float4 t1 = *(const float4*)&g_t[(size_t)nrow * O + o0 + tx * 8 + 4];
        tv[0]=t0.x; tv[1]=t0.y; tv[2]=t0.z; tv[3]=t0.w;
        tv[4]=t1.x; tv[5]=t1.y; tv[6]=t1.z; tv[7]=t1.w;
#pragma unroll
        for (int i = 0; i < 5; ++i) {
            int nbr = sidx[ty * 5 + i];
            float4 v0 = *(const float4*)&g_t2[(size_t)(b * NN + nbr) * O + o0 + tx * 8];
            float4 v1 = *(const float4*)&g_t2[(size_t)(b * NN + nbr) * O + o0 + tx * 8 + 4];
            hv[i][0]=v0.x; hv[i][1]=v0.y; hv[i][2]=v0.z; hv[i][3]=v0.w;
            hv[i][4]=v1.x; hv[i][5]=v1.y; hv[i][6]=v1.z; hv[i][7]=v1.w;
        }
    } else {
#pragma unroll
        for (int j = 0; j < 8; ++j) tv[j] = 0.f;
#pragma unroll
        for (int i = 0; i < 5; ++i)
#pragma unroll
            for (int j = 0; j < 8; ++j) hv[i][j] = 0.f;
    }
#pragma unroll
    for (int j = 0; j < 8; ++j) {
        float tval = tv[j];
        float mx = -3.402823466e38f, s = 0.f, q = 0.f;
#pragma unroll
        for (int i = 0; i < 5; ++i) {
            float h = hv[i][j] + tval;
            mx = fmaxf(mx, h);
            s += h;
            q += h * h;
        }
        redM[ty][tx * 8 + j] = mx;
        redS[ty][tx * 8 + j] = s;
        redQ[ty][tx * 8 + j] = q;
    }
    __syncthreads();
    for (int t = tid; t < 512; t += 256) {
        int pp = t >> 7, col = t & 127;
        float m0 = fmaxf(redM[pp * 4 + 0][col], redM[pp * 4 + 1][col]);
        float m1 = fmaxf(redM[pp * 4 + 2][col], redM[pp * 4 + 3][col]);
        if (o0 + col < O)
            g_cat[(size_t)(b * NN + n0 + pp) * CATC + outoff + o0 + col] = fmaxf(m0, m1);
    }
    if (tid < 128) {
        float s = 0.f, q = 0.f;
#pragma unroll
        for (int yy = 0; yy < 16; ++yy) { s += redS[yy][tid]; q += redQ[yy][tid]; }
        size_t pidx = (((size_t)b * gridDim.x + blockIdx.x) * (NN / 4) + blockIdx.y) * 128 + tid;
        g_partS[pidx] = s;
        g_partQ[pidx] = q;
    }
}

// ---------------- reduce gather partials -> g_sum/g_sumsq ----------------
__global__ void reduce_conv(int O, int oT) {
    int i = blockIdx.x * 256 + threadIdx.x;
    if (i >= BB * O) return;
    int b = i / O, o = i - b * O;
    int ot = o >> 7, col = o & 127;
    float s = 0.f, q = 0.f;
    for (int ny = 0; ny < NN / 4; ++ny) {
        size_t p = (((size_t)b * oT + ot) * (NN / 4) + ny) * 128 + col;
        s += g_partS[p];
        q += g_partQ[p];
    }
    g_sum[i] = s;
    g_sumsq[i] = q;
}

// ---------------- finalize edge conv (layer 4 only): instnorm + leaky, in place -------
__global__ void finalize_conv(int O, int outoff) {
    int i = blockIdx.x * 256 + threadIdx.x;
    if (i >= BB * NN * O) return;
    int row = i / O;
    int o = i - row * O;
    int b = row >> 11;
    const float cnt = (float)(NN * KK);
    float mean = g_sum[b * O + o] / cnt;
    float var = fmaxf(g_sumsq[b * O + o] / cnt - mean * mean, 0.f);
    float inv = rsqrtf(var + 1e-5f);
    size_t pidx = (size_t)row * CATC + outoff + o;
    float v = (g_cat[pidx] - mean) * inv;
    g_cat[pidx] = v >= 0.f ? v : 0.2f * v;
}

// ---------------- fused finalize (layers 1-3): instnorm + leaky in place AND
//                  next layer's xx (row sum of squares, c-ascending = bit-exact) -------
__global__ void finalize_xx(int O, int outoff) {
    __shared__ float X[64][129];
    int row0 = blockIdx.x * 64;
    int b = row0 >> 11;   // row0 / NN
    int tid = threadIdx.x;
    const float cnt = (float)(NN * KK);
    for (int idx = tid; idx < 64 * O; idx += 256) {
        int r = idx / O, c = idx - r * O;
        float mean = g_sum[b * O + c] / cnt;
        float var = fmaxf(g_sumsq[b * O + c] / cnt - mean * mean, 0.f);
        float inv = rsqrtf(var + 1e-5f);
        size_t pidx = (size_t)(row0 + r) * CATC + outoff + c;
        float v = (g_cat[pidx] - mean) * inv;
        v = v >= 0.f ? v : 0.2f * v;
        X[r][c] = v;
        g_cat[pidx] = v;
    }
    __syncthreads();
    if (tid < 64) {
        float s = 0.f;
        for (int c = 0; c < O; ++c) s += X[tid][c] * X[tid][c];
        g_xx[row0 + tid] = s;
    }
}

// ---------------- final conv GEMM: 128x128 tile, reg prefetch + float4 ----------------
__global__ void final_gemm(const float* __restrict__ w5) {
    __shared__ __align__(16) float As[16][132];
    __shared__ __align__(16) float Bs[16][132];
    __shared__ float redS[16][128];
    __shared__ float redQ[16][128];
    int r0 = blockIdx.y * 128, o0 = blockIdx.x * 128;
    int tid = threadIdx.x, tx = tid & 15, ty = tid >> 4;
    float acc[8][8] = {};
    float4 rg[4];
#pragma unroll
    for (int ii = 0; ii < 4; ++ii) {
        int q4 = tid + ii * 256;
        int which = q4 >> 9, r = (q4 & 511) >> 2, cc4 = q4 & 3;
        rg[ii] = which ? *(const float4*)&w5[(size_t)(o0 + r) * 512 + cc4 * 4]
                       : *(const float4*)&g_cat[(size_t)(r0 + r) * CATC + cc4 * 4];
    }
#pragma unroll 1
    for (int ch = 0; ch < 32; ++ch) {
#pragma unroll
        for (int ii = 0; ii < 4; ++ii) {
            int q4 = tid + ii * 256;
            int which = q4 >> 9, r = (q4 & 511) >> 2, cc4 = q4 & 3;
            float4 v = rg[ii];
            if (which) {
                Bs[cc4 * 4 + 0][r] = v.x; Bs[cc4 * 4 + 1][r] = v.y;
                Bs[cc4 * 4 + 2][r] = v.z; Bs[cc4 * 4 + 3][r] = v.w;
            } else {
                As[cc4 * 4 + 0][r] = v.x; As[cc4 * 4 + 1][r] = v.y;
                As[cc4 * 4 + 2][r] = v.z; As[cc4 * 4 + 3][r] = v.w;
            }
        }
        __syncthreads();
        if (ch + 1 < 32) {
            int c0 = (ch + 1) * 16;
#pragma unroll
            for (int ii = 0; ii < 4; ++ii) {
                int q4 = tid + ii * 256;
                int which = q4 >> 9, r = (q4 & 511) >> 2, cc4 = q4 & 3;
                rg[ii] = which ? *(const float4*)&w5[(size_t)(o0 + r) * 512 + c0 + cc4 * 4]
                               : *(const float4*)&g_cat[(size_t)(r0 + r) * CATC + c0 + cc4 * 4];
            }
        }
#pragma unroll
        for (int cc = 0; cc < 16; ++cc) {
            float4 a0 = *(const float4*)&As[cc][ty * 8];
            float4 a1 = *(const float4*)&As[cc][ty * 8 + 4];
            float4 b0 = *(const float4*)&Bs[cc][tx * 8];
            float4 b1 = *(const float4*)&Bs[cc][tx * 8 + 4];
            float aa[8] = {a0.x, a0.y, a0.z, a0.w, a1.x, a1.y, a1.z, a1.w};
            float bb[8] = {b0.x, b0.y, b0.z, b0.w, b1.x, b1.y, b1.z, b1.w};
#pragma unroll
            for (int i = 0; i < 8; ++i)
#pragma unroll
                for (int j = 0; j < 8; ++j)
                    acc[i][j] = fmaf(aa[i], bb[j], acc[i][j]);
        }
        __syncthreads();
    }
    float ls[8] = {}, lq[8] = {};
#pragma unroll
    for (int i = 0; i < 8; ++i) {
        size_t base = (size_t)(r0 + ty * 8 + i) * 512 + o0 + tx * 8;
        *(float4*)&g_h5[base] = make_float4(acc[i][0], acc[i][1], acc[i][2], acc[i][3]);
        *(float4*)&g_h5[base + 4] = make_float4(acc[i][4], acc[i][5], acc[i][6], acc[i][7]);
#pragma unroll
        for (int j = 0; j < 8; ++j) { ls[j] += acc[i][j]; lq[j] += acc[i][j] * acc[i][j]; }
    }
#pragma unroll
    for (int j = 0; j < 8; ++j) { redS[ty][tx * 8 + j] = ls[j]; redQ[ty][tx * 8 + j] = lq[j]; }
    __syncthreads();
    if (tid < 128) {
        float s = 0.f, q = 0.f;
#pragma unroll
        for (int yy = 0; yy < 16; ++yy) { s += redS[yy][tid]; q += redQ[yy][tid]; }
        size_t p = ((size_t)blockIdx.y * 4 + blockIdx.x) * 128 + tid;
        g_partS[p] = s;
        g_partQ[p] = q;
    }
}

__global__ void reduce_final() {
    int i = blockIdx.x * 256 + threadIdx.x;
    if (i >= BB * 512) return;
    int b = i >> 9, o = i & 511;
    int ox = o >> 7, col = o & 127;
    float s = 0.f, q = 0.f;
    for (int yy = 0; yy < 16; ++yy) {
        size_t p = ((size_t)(b * 16 + yy) * 4 + ox) * 128 + col;
        s += g_partS[p];
        q += g_partQ[p];
    }
    g_sum[i] = s;
    g_sumsq[i] = q;
}

// ---------------- final normalize + leaky + transpose to (B,512,N), 32x32 tiles -------
__global__ void finalize_final(float* __restrict__ out) {
    __shared__ float S[32][33];
    int n0 = blockIdx.x * 32, o0 = blockIdx.y * 32, b = blockIdx.z;
    int tx = threadIdx.x;        // 0..31
    int ty = threadIdx.y;        // 0..7
    const float cnt = (float)NN;
    float mean, inv;
    {
        int o = o0 + tx;
        mean = g_sum[b * 512 + o] / cnt;
        float var = fmaxf(g_sumsq[b * 512 + o] / cnt - mean * mean, 0.f);
        inv = rsqrtf(var + 1e-5f);
    }
#pragma unroll
    for (int ph = 0; ph < 4; ++ph) {
        int nl = ty + ph * 8;
        float v = (g_h5[(size_t)(b * NN + n0 + nl) * 512 + o0 + tx] - mean) * inv;
        v = v >= 0.f ? v : 0.2f * v;
        S[tx][nl] = v;
    }
    __syncthreads();
#pragma unroll
    for (int ph = 0; ph < 4; ++ph) {
        int ol = ty + ph * 8;
        out[((size_t)b * 512 + o0 + ol) * NN + n0 + tx] = S[ol][tx];
    }
}

// ---------------- host orchestration ----------------
// last_layer: 0 -> finalize fused with next layer's xx; 1 -> plain finalize
static void run_edge(const float* xin, int use_in, int xoff, int C,
                     const float* w, int O, int outoff, int last_layer) {
    dist_gemm<<<dim3(136, 1, BB), 256>>>(xin, use_in, xoff, C);
    topk_kernel<<<dim3(NN, BB), 256>>>();
    if (C == 128 && O == 256) {
        small_gemm<<<dim3((O + 63) / 64, (BB * NN) / 64), 256>>>(xin, use_in, xoff, C, w, O, 0);
        wx_gemm128<<<dim3(O / 128, (BB * NN) / 128), 256>>>(w, xoff, O);
    } else {
        small_gemm2<<<dim3((O + 63) / 64, (BB * NN) / 64), 256>>>(xin, use_in, xoff, C, w, O);
    }
    int oT = (O + 127) / 128;
    edge_epilogue<<<dim3(oT, NN / 4, BB), 256>>>(O, outoff);
    reduce_conv<<<(BB * O + 255) / 256, 256>>>(O, oT);
    if (last_layer)
        finalize_conv<<<(BB * NN * O + 255) / 256, 256>>>(O, outoff);
    else
        finalize_xx<<<BB * NN / 64, 256>>>(O, outoff);   // also produces next layer's g_xx
}

extern "C" void kernel_launch(void* const* d_in, const int* in_sizes, int n_in,
                              void* d_out, int out_size) {
    const float* x  = (const float*)d_in[0];
    const float* w1 = (const float*)d_in[1];
    const float* w2 = (const float*)d_in[2];
    const float* w3 = (const float*)d_in[3];
    const float* w4 = (const float*)d_in[4];
    const float* w5 = (const float*)d_in[5];
    float* out = (float*)d_out;

    xx_in<<<(BB * NN + 255) / 256, 256>>>(x);
    run_edge(x, 1, 0,   3,   w1, 64,  0,   0);   // x1 -> cat[:, :,   0: 64]; xx for L2
    run_edge(x, 0, 0,   64,  w2, 64,  64,  0);   // x2 -> cat[:, :,  64:128]; xx for L3
    run_edge(x, 0, 64,  64,  w3, 128, 128, 0);   // x3 -> cat[:, :, 128:256]; xx for L4
    run_edge(x, 0, 128, 128, w4, 256, 256, 1);   // x4 -> cat[:, :, 256:512]

    final_gemm<<<dim3(512 / 128, (BB * NN) / 128), 256>>>(w5);
    reduce_final<<<(BB * 512 + 255) / 256, 256>>>();
    finalize_final<<<dim3(NN / 32, 512 / 32, BB), dim3(32, 8)>>>(out);
}